// round 1
// baseline (speedup 1.0000x reference)
#include <cuda_runtime.h>
#include <math.h>

#define BB   8
#define CIN  512
#define CK   256
#define CV   512
#define HW   4096
#define SS   110

// Scratch (allocation-free rule: __device__ globals)
__device__ __align__(16) float g_qk   [BB*CK*HW];   // [b][c][n]  32MB
__device__ __align__(16) float g_val  [BB*CV*HW];   // [b][c][n]  64MB
__device__ __align__(16) float g_key  [BB*CK*SS];   // [b][c][s]
__device__ __align__(16) float g_value[BB*SS*CV];   // [b][s][c]
__device__ __align__(16) float g_p    [BB*SS*HW];   // [b][s][n]  14MB
__device__ __align__(16) float g_y    [BB*CV*HW];   // [b][c][n]  64MB

// ---------------------------------------------------------------------------
// conv1x1 + BN (+ReLU) (+residual):
//   out[b,m,n] = act( s[m]*sum_k W[m,k]*X[b,k,n] + t[m] ) (+ resid[b,m,n])
// GEMM: A = W [M,512] row-major, B = X[b] [512,4096] row-major.
// 128x128x16 tile, 256 threads, 8x8 per-thread register tile.
// ---------------------------------------------------------------------------
template<bool RELU, bool RESID>
__global__ __launch_bounds__(256) void conv_bn_kernel(
    const float* __restrict__ W, const float* __restrict__ X,
    const float* __restrict__ gamma, const float* __restrict__ beta,
    const float* __restrict__ mean,  const float* __restrict__ var,
    const float* __restrict__ resid, float* __restrict__ out, int M)
{
    __shared__ __align__(16) float As[16][128];
    __shared__ __align__(16) float Bs[16][128];

    const int tid = threadIdx.x;
    const int n0  = blockIdx.x * 128;
    const int m0  = blockIdx.y * 128;
    const size_t boff = (size_t)blockIdx.z * CIN * HW;
    const float* Xb = X + boff;

    const int tm = tid >> 4;   // 0..15 (m)
    const int tn = tid & 15;   // 0..15 (n)

    float acc[8][8];
    #pragma unroll
    for (int i = 0; i < 8; ++i)
        #pragma unroll
        for (int j = 0; j < 8; ++j) acc[i][j] = 0.f;

    for (int kt = 0; kt < CIN / 16; ++kt) {
        // A tile: 128 rows x 16 k  (512 float4)
        #pragma unroll
        for (int p = 0; p < 2; ++p) {
            int idx = p * 256 + tid;
            int row = idx >> 2, kq = idx & 3;
            float4 v = *(const float4*)(W + (size_t)(m0 + row) * CIN + kt * 16 + kq * 4);
            As[kq*4+0][row] = v.x; As[kq*4+1][row] = v.y;
            As[kq*4+2][row] = v.z; As[kq*4+3][row] = v.w;
        }
        // B tile: 16 k x 128 n
        #pragma unroll
        for (int p = 0; p < 2; ++p) {
            int idx = p * 256 + tid;
            int kr = idx >> 5, c4 = idx & 31;
            *(float4*)&Bs[kr][c4*4] =
                *(const float4*)(Xb + (size_t)(kt*16 + kr) * HW + n0 + c4*4);
        }
        __syncthreads();

        #pragma unroll
        for (int kk = 0; kk < 16; ++kk) {
            float a[8], bv[8];
            *(float4*)(a)    = *(float4*)&As[kk][tm*8];
            *(float4*)(a+4)  = *(float4*)&As[kk][tm*8+4];
            *(float4*)(bv)   = *(float4*)&Bs[kk][tn*8];
            *(float4*)(bv+4) = *(float4*)&Bs[kk][tn*8+4];
            #pragma unroll
            for (int i = 0; i < 8; ++i)
                #pragma unroll
                for (int j = 0; j < 8; ++j)
                    acc[i][j] += a[i] * bv[j];
        }
        __syncthreads();
    }

    const size_t ooff = (size_t)blockIdx.z * M * HW;
    #pragma unroll
    for (int i = 0; i < 8; ++i) {
        int co = m0 + tm*8 + i;
        float sc = gamma[co] * rsqrtf(var[co] + 1e-5f);
        float tt = beta[co] - mean[co] * sc;
        float v[8];
        #pragma unroll
        for (int j = 0; j < 8; ++j) {
            float z = acc[i][j] * sc + tt;
            if (RELU) z = fmaxf(z, 0.f);
            v[j] = z;
        }
        int n = n0 + tn*8;
        if (RESID) {
            const float* rp = resid + ooff + (size_t)co * HW + n;
            float4 r0 = *(const float4*)rp, r1 = *(const float4*)(rp + 4);
            v[0]+=r0.x; v[1]+=r0.y; v[2]+=r0.z; v[3]+=r0.w;
            v[4]+=r1.x; v[5]+=r1.y; v[6]+=r1.z; v[7]+=r1.w;
        }
        float* op = out + ooff + (size_t)co * HW + n;
        *(float4*)op     = make_float4(v[0], v[1], v[2], v[3]);
        *(float4*)(op+4) = make_float4(v[4], v[5], v[6], v[7]);
    }
}

// ---------------------------------------------------------------------------
// PSP adaptive max pool over a 64x64 plane -> 110 cells (s = 1,3,6,8).
// One block per (b,c) plane; plane staged in smem.
// transposed=0: out[b][c][cell] ; transposed=1: out[b][cell][c]
// ---------------------------------------------------------------------------
__global__ __launch_bounds__(128) void psp_kernel(
    const float* __restrict__ in, float* __restrict__ out, int C, int transposed)
{
    __shared__ __align__(16) float sp[4096];
    __shared__ float s8v[64];
    const int bc = blockIdx.x;
    const int b = bc / C, c = bc - b * C;
    const float* plane = in + (size_t)bc * 4096;
    for (int i = threadIdx.x; i < 1024; i += 128)
        ((float4*)sp)[i] = ((const float4*)plane)[i];
    __syncthreads();

    const int tid = threadIdx.x;
    float m = -3.402823e38f;
    int cell = -1;

    if (tid < 64) {                       // s = 8 : exact 8x8 windows
        int i = tid >> 3, j = tid & 7;
        for (int rr = i*8; rr < i*8+8; ++rr)
            for (int cc = j*8; cc < j*8+8; ++cc)
                m = fmaxf(m, sp[rr*64 + cc]);
        s8v[tid] = m;
        cell = 46 + tid;
    } else if (tid < 100) {               // s = 6
        const int st[6] = {0,10,21,32,42,53};
        const int en[6] = {11,22,32,43,54,64};
        int t = tid - 64, i = t / 6, j = t - i*6;
        for (int rr = st[i]; rr < en[i]; ++rr)
            for (int cc = st[j]; cc < en[j]; ++cc)
                m = fmaxf(m, sp[rr*64 + cc]);
        cell = 10 + t;
    } else if (tid < 109) {               // s = 3
        const int st[3] = {0,21,42};
        const int en[3] = {22,43,64};
        int t = tid - 100, i = t / 3, j = t - i*3;
        for (int rr = st[i]; rr < en[i]; ++rr)
            for (int cc = st[j]; cc < en[j]; ++cc)
                m = fmaxf(m, sp[rr*64 + cc]);
        cell = 1 + t;
    }

    if (cell >= 0) {
        size_t o = transposed ? ((size_t)b*SS*C + (size_t)cell*C + c)
                              : ((size_t)bc*SS + cell);
        out[o] = m;
    }
    __syncthreads();
    if (tid == 0) {                       // s = 1 from the 64 exact 8x8 cells
        float mm = s8v[0];
        for (int i = 1; i < 64; ++i) mm = fmaxf(mm, s8v[i]);
        size_t o = transposed ? ((size_t)b*SS*C + c) : ((size_t)bc*SS);
        out[o] = mm;
    }
}

// ---------------------------------------------------------------------------
// scores = softmax( (qk[b]^T @ key[b]) / 16 )  -> g_p [b][s][n]
// Block: 64 rows (n) x full S=110, 256 threads.
// Dyn smem: key [c][s] 256*110, qT [c][r] 256*64, scores [r][112].
// ---------------------------------------------------------------------------
#define SM_KEY 0
#define SM_Q   (CK*SS)            // 28160
#define SM_S   (CK*SS + CK*64)    // 44544
#define SMEM_ATTN ((CK*SS + CK*64 + 64*112) * 4)  // 206848 bytes

__global__ __launch_bounds__(256) void attn_scores_kernel(
    const float* __restrict__ qk, const float* __restrict__ key, float* __restrict__ p)
{
    extern __shared__ __align__(16) float sm[];
    float* sKey = sm + SM_KEY;
    float* sQ   = sm + SM_Q;
    float* sS   = sm + SM_S;

    const int b = blockIdx.y, n0 = blockIdx.x * 64;
    const int tid = threadIdx.x;

    const float* kb = key + (size_t)b * CK * SS;
    for (int i = tid; i < (CK*SS)/4; i += 256)
        ((float4*)sKey)[i] = ((const float4*)kb)[i];

    const float* qb = qk + (size_t)b * CK * HW;
    for (int i = tid; i < CK * 16; i += 256) {
        int c = i >> 4, r4 = i & 15;
        *(float4*)&sQ[c*64 + r4*4] = *(const float4*)&qb[(size_t)c*HW + n0 + r4*4];
    }
    __syncthreads();

    const int ty = tid >> 4, tx = tid & 15;   // 4 rows per ty, s = tx + 16u
    float acc[4][7];
    #pragma unroll
    for (int i = 0; i < 4; ++i)
        #pragma unroll
        for (int u = 0; u < 7; ++u) acc[i][u] = 0.f;

    for (int c = 0; c < CK; ++c) {
        float4 qv = *(float4*)&sQ[c*64 + ty*4];
        float q[4] = {qv.x, qv.y, qv.z, qv.w};
        #pragma unroll
        for (int u = 0; u < 7; ++u) {
            int s = tx + u*16;                 // may exceed 109; discarded at write
            float kv = sKey[c*SS + s];
            #pragma unroll
            for (int i = 0; i < 4; ++i) acc[i][u] += q[i] * kv;
        }
    }

    #pragma unroll
    for (int u = 0; u < 7; ++u) {
        int s = tx + u*16;
        if (s < SS) {
            #pragma unroll
            for (int i = 0; i < 4; ++i)
                sS[(ty*4 + i)*112 + s] = acc[i][u] * 0.0625f;  // Ck^-0.5 = 1/16
        }
    }
    __syncthreads();

    if (tid < 64) {                            // softmax, one row per thread
        float mx = -3.402823e38f;
        for (int s = 0; s < SS; ++s) mx = fmaxf(mx, sS[tid*112 + s]);
        float sum = 0.f;
        for (int s = 0; s < SS; ++s) {
            float e = __expf(sS[tid*112 + s] - mx);
            sS[tid*112 + s] = e; sum += e;
        }
        float inv = 1.f / sum;
        for (int s = 0; s < SS; ++s) sS[tid*112 + s] *= inv;
    }
    __syncthreads();

    float* pb = p + (size_t)b * SS * HW;
    for (int i = tid; i < SS*64; i += 256) {
        int s = i >> 6, r = i & 63;
        pb[(size_t)s*HW + n0 + r] = sS[r*112 + s];
    }
}

// ---------------------------------------------------------------------------
// y[b][c][n] = sum_s P[b][s][n] * value[b][s][c]   (output already transposed
// to channel-major for the final conv). 64x64 tile, K=110 fully in smem.
// ---------------------------------------------------------------------------
__global__ __launch_bounds__(256) void attn_out_kernel(
    const float* __restrict__ p, const float* __restrict__ value, float* __restrict__ y)
{
    __shared__ __align__(16) float sP[SS*64];   // [k][r]
    __shared__ __align__(16) float sV[SS*64];   // [k][c]
    const int b = blockIdx.z, n0 = blockIdx.x * 64, c0 = blockIdx.y * 64;
    const int tid = threadIdx.x;

    const float* pb = p + (size_t)b * SS * HW;
    const float* vb = value + (size_t)b * SS * CV;
    for (int i = tid; i < SS*16; i += 256) {
        int k = i >> 4, r4 = i & 15;
        *(float4*)&sP[k*64 + r4*4] = *(const float4*)&pb[(size_t)k*HW + n0 + r4*4];
        *(float4*)&sV[k*64 + r4*4] = *(const float4*)&vb[(size_t)k*CV + c0 + r4*4];
    }
    __syncthreads();

    const int tm = tid >> 4, tn = tid & 15;     // tm: n, tn: c
    float acc[4][4];
    #pragma unroll
    for (int i = 0; i < 4; ++i)
        #pragma unroll
        for (int j = 0; j < 4; ++j) acc[i][j] = 0.f;

    for (int k = 0; k < SS; ++k) {
        float4 pv = *(float4*)&sP[k*64 + tm*4];
        float4 vv = *(float4*)&sV[k*64 + tn*4];
        float pa[4] = {pv.x, pv.y, pv.z, pv.w};
        float va[4] = {vv.x, vv.y, vv.z, vv.w};
        #pragma unroll
        for (int i = 0; i < 4; ++i)
            #pragma unroll
            for (int j = 0; j < 4; ++j)
                acc[i][j] += pa[i] * va[j];
    }

    float* yb = y + (size_t)b * CV * HW;
    #pragma unroll
    for (int j = 0; j < 4; ++j) {
        float4 o = make_float4(acc[0][j], acc[1][j], acc[2][j], acc[3][j]);
        *(float4*)&yb[(size_t)(c0 + tn*4 + j)*HW + n0 + tm*4] = o;
    }
}

// ---------------------------------------------------------------------------
extern "C" void kernel_launch(void* const* d_in, const int* in_sizes, int n_in,
                              void* d_out, int out_size)
{
    const float* x        = (const float*)d_in[0];
    const float* qk_w     = (const float*)d_in[1];
    const float* qk_gamma = (const float*)d_in[2];
    const float* qk_beta  = (const float*)d_in[3];
    const float* qk_mean  = (const float*)d_in[4];
    const float* qk_var   = (const float*)d_in[5];
    const float* v_w      = (const float*)d_in[6];
    const float* v_gamma  = (const float*)d_in[7];
    const float* v_beta   = (const float*)d_in[8];
    const float* v_mean   = (const float*)d_in[9];
    const float* v_var    = (const float*)d_in[10];
    const float* out_w    = (const float*)d_in[11];
    const float* o_gamma  = (const float*)d_in[12];
    const float* o_beta   = (const float*)d_in[13];
    const float* o_mean   = (const float*)d_in[14];
    const float* o_var    = (const float*)d_in[15];
    float* out = (float*)d_out;

    float *qk, *val, *key, *value, *p, *y;
    cudaGetSymbolAddress((void**)&qk,    g_qk);
    cudaGetSymbolAddress((void**)&val,   g_val);
    cudaGetSymbolAddress((void**)&key,   g_key);
    cudaGetSymbolAddress((void**)&value, g_value);
    cudaGetSymbolAddress((void**)&p,     g_p);
    cudaGetSymbolAddress((void**)&y,     g_y);

    // 1) qk = relu(bn(conv(x, qk_w)))   [8,256,4096]
    conv_bn_kernel<true, false><<<dim3(32, 2, 8), 256>>>(
        qk_w, x, qk_gamma, qk_beta, qk_mean, qk_var, nullptr, qk, CK);
    // 2) val = relu(bn(conv(x, v_w)))   [8,512,4096]
    conv_bn_kernel<true, false><<<dim3(32, 4, 8), 256>>>(
        v_w, x, v_gamma, v_beta, v_mean, v_var, nullptr, val, CV);
    // 3) key = psp(qk)  [8,256,110];  value = psp(val)^T  [8,110,512]
    psp_kernel<<<BB * CK, 128>>>(qk,  key,   CK, 0);
    psp_kernel<<<BB * CV, 128>>>(val, value, CV, 1);
    // 4) P = softmax(q @ key / 16)  -> [8,110,4096]
    cudaFuncSetAttribute(attn_scores_kernel,
                         cudaFuncAttributeMaxDynamicSharedMemorySize, SMEM_ATTN);
    attn_scores_kernel<<<dim3(64, 8), 256, SMEM_ATTN>>>(qk, key, p);
    // 5) y[c][n] = sum_s P[s][n] * value[s][c]
    attn_out_kernel<<<dim3(64, 8, 8), 256>>>(p, value, y);
    // 6) out = x + bn(conv(y, out_w))
    conv_bn_kernel<false, true><<<dim3(32, 4, 8), 256>>>(
        out_w, y, o_gamma, o_beta, o_mean, o_var, x, out, CIN);
}

// round 3
// speedup vs baseline: 1.6572x; 1.6572x over previous
#include <cuda_runtime.h>
#include <cstdint>
#include <math.h>

#define BB   8
#define CIN  512
#define CK   256
#define CV   512
#define HW   4096
#define SS   110

// Scratch (allocation-free rule: __device__ globals)
__device__ __align__(16) float g_qk   [BB*CK*HW];   // [b][c][n]
__device__ __align__(16) float g_val  [BB*CV*HW];   // [b][c][n]
__device__ __align__(16) float g_xc   [BB*CIN*HW];  // tf32-rounded x, [b][k][n]
__device__ __align__(16) float g_y    [BB*CV*HW];   // [b][c][n] tf32-rounded
__device__ __align__(16) float g_key  [BB*CK*SS];   // [b][c][s]
__device__ __align__(16) float g_value[BB*SS*CV];   // [b][s][c]
__device__ __align__(16) float g_p    [BB*SS*HW];   // [b][s][n]
__device__ __align__(16) float g_wq   [CK*CIN];     // tf32-rounded weights
__device__ __align__(16) float g_wv   [CV*CIN];
__device__ __align__(16) float g_wo   [CIN*CV];

// ---------------------------------------------------------------------------
__device__ __forceinline__ uint32_t smem_u32(const void* p) {
    uint32_t a;
    asm("{ .reg .u64 t; cvta.to.shared.u64 t, %1; cvt.u32.u64 %0, t; }" : "=r"(a) : "l"(p));
    return a;
}
__device__ __forceinline__ float cvt_tf32(float v) {
    uint32_t u;
    asm("cvt.rna.tf32.f32 %0, %1;" : "=r"(u) : "f"(v));
    return __uint_as_float(u);
}
__device__ __forceinline__ void mma_tf32(float* c, const uint32_t* a, const uint32_t* b) {
    asm volatile(
        "mma.sync.aligned.m16n8k8.row.col.f32.tf32.tf32.f32 "
        "{%0,%1,%2,%3}, {%4,%5,%6,%7}, {%8,%9}, {%0,%1,%2,%3};"
        : "+f"(c[0]), "+f"(c[1]), "+f"(c[2]), "+f"(c[3])
        : "r"(a[0]), "r"(a[1]), "r"(a[2]), "r"(a[3]), "r"(b[0]), "r"(b[1]));
}

// ---------------------------------------------------------------------------
// conv1x1 + BN (+ReLU)(+residual) via tf32 mma.sync.
// out[b,m,n] = act( s[m]*sum_k W[m,k]*X[b,k,n] + t[m] ) (+ resid)
// CTA: 128m x 128n, 8 warps (2m x 4n), warp tile 64m x 32n.
// K staged 32 at a time, double-buffered cp.async.
// smem A: [m][k] stride 36 floats;  smem B: [k][n] stride 136 floats.
// ---------------------------------------------------------------------------
#define A_STR 36
#define B_STR 136
#define A_TILE_B (128*A_STR*4)             // 18432
#define B_TILE_B (32*B_STR*4)              // 17408
#define STAGE_B  (A_TILE_B + B_TILE_B)     // 35840
#define STAGE_F  (STAGE_B/4)
#define CONV_SMEM (2*STAGE_B)              // 71680

template<bool RELU, bool RESID>
__global__ __launch_bounds__(256) void conv_mma_kernel(
    const float* __restrict__ W, const float* __restrict__ X,
    const float* __restrict__ gamma, const float* __restrict__ beta,
    const float* __restrict__ mean,  const float* __restrict__ var,
    const float* __restrict__ resid, float* __restrict__ out, int M)
{
    extern __shared__ __align__(16) float smf[];
    const uint32_t sb = smem_u32(smf);
    const int tid = threadIdx.x;
    const int lane = tid & 31;
    const int wid  = tid >> 5;
    const int gidr = lane >> 2, t4 = lane & 3;
    const int wm = wid >> 2, wn = wid & 3;            // 2 x 4 warp grid
    const int n0 = blockIdx.x * 128, m0 = blockIdx.y * 128, b = blockIdx.z;

    const float* gW = W + (size_t)m0 * CIN;
    const float* gX = X + (size_t)b * CIN * HW + n0;

    auto load_stage = [&](int s) {
        const uint32_t base = sb + (uint32_t)(s & 1) * STAGE_B;
        const float* ga = gW + s * 32;
        const float* gb = gX + (size_t)s * 32 * HW;
        #pragma unroll
        for (int i = 0; i < 4; ++i) {               // A: 1024 float4
            int idx = i * 256 + tid;
            int r = idx >> 3, c = idx & 7;
            asm volatile("cp.async.cg.shared.global [%0], [%1], 16;"
                :: "r"(base + (uint32_t)(r * A_STR + c * 4) * 4),
                   "l"(ga + (size_t)r * CIN + c * 4));
        }
        #pragma unroll
        for (int i = 0; i < 4; ++i) {               // B: 1024 float4
            int idx = i * 256 + tid;
            int r = idx >> 5, c = idx & 31;
            asm volatile("cp.async.cg.shared.global [%0], [%1], 16;"
                :: "r"(base + A_TILE_B + (uint32_t)(r * B_STR + c * 4) * 4),
                   "l"(gb + (size_t)r * HW + c * 4));
        }
        asm volatile("cp.async.commit_group;" ::: "memory");
    };

    float acc[4][4][4];
    #pragma unroll
    for (int mt = 0; mt < 4; ++mt)
        #pragma unroll
        for (int nt = 0; nt < 4; ++nt)
            #pragma unroll
            for (int r = 0; r < 4; ++r) acc[mt][nt][r] = 0.f;

    load_stage(0);

    for (int kt = 0; kt < 16; ++kt) {
        if (kt + 1 < 16) {
            load_stage(kt + 1);
            asm volatile("cp.async.wait_group 1;" ::: "memory");
        } else {
            asm volatile("cp.async.wait_group 0;" ::: "memory");
        }
        __syncthreads();

        const float* sA = smf + (kt & 1) * STAGE_F;
        const float* sB = sA + 128 * A_STR;
        #pragma unroll
        for (int s = 0; s < 4; ++s) {
            const int kk = s * 8;
            uint32_t af[4][4], bf[4][2];
            #pragma unroll
            for (int mt = 0; mt < 4; ++mt) {
                int r = wm * 64 + mt * 16 + gidr;
                af[mt][0] = __float_as_uint(sA[r * A_STR + kk + t4]);
                af[mt][1] = __float_as_uint(sA[(r + 8) * A_STR + kk + t4]);
                af[mt][2] = __float_as_uint(sA[r * A_STR + kk + t4 + 4]);
                af[mt][3] = __float_as_uint(sA[(r + 8) * A_STR + kk + t4 + 4]);
            }
            #pragma unroll
            for (int nt = 0; nt < 4; ++nt) {
                int cc = wn * 32 + nt * 8 + gidr;
                bf[nt][0] = __float_as_uint(sB[(kk + t4) * B_STR + cc]);
                bf[nt][1] = __float_as_uint(sB[(kk + t4 + 4) * B_STR + cc]);
            }
            #pragma unroll
            for (int mt = 0; mt < 4; ++mt)
                #pragma unroll
                for (int nt = 0; nt < 4; ++nt)
                    mma_tf32(acc[mt][nt], af[mt], bf[nt]);
        }
        __syncthreads();
    }

    // Epilogue: BN (+ReLU) (+residual)
    const size_t bo = (size_t)b * M * HW;
    #pragma unroll
    for (int mt = 0; mt < 4; ++mt) {
        const int ml = m0 + wm * 64 + mt * 16 + gidr;
        const int mh = ml + 8;
        const float scl = gamma[ml] * rsqrtf(var[ml] + 1e-5f);
        const float ttl = beta[ml] - mean[ml] * scl;
        const float sch = gamma[mh] * rsqrtf(var[mh] + 1e-5f);
        const float tth = beta[mh] - mean[mh] * sch;
        #pragma unroll
        for (int nt = 0; nt < 4; ++nt) {
            const int nn = n0 + wn * 32 + nt * 8 + 2 * t4;
            float2 vl, vh;
            vl.x = acc[mt][nt][0] * scl + ttl;
            vl.y = acc[mt][nt][1] * scl + ttl;
            vh.x = acc[mt][nt][2] * sch + tth;
            vh.y = acc[mt][nt][3] * sch + tth;
            if (RELU) {
                vl.x = fmaxf(vl.x, 0.f); vl.y = fmaxf(vl.y, 0.f);
                vh.x = fmaxf(vh.x, 0.f); vh.y = fmaxf(vh.y, 0.f);
            }
            if (RESID) {
                float2 rl = *(const float2*)(resid + bo + (size_t)ml * HW + nn);
                float2 rh = *(const float2*)(resid + bo + (size_t)mh * HW + nn);
                vl.x += rl.x; vl.y += rl.y; vh.x += rh.x; vh.y += rh.y;
            }
            *(float2*)(out + bo + (size_t)ml * HW + nn) = vl;
            *(float2*)(out + bo + (size_t)mh * HW + nn) = vh;
        }
    }
}

// ---------------------------------------------------------------------------
// Elementwise fp32 -> tf32 rounding
// ---------------------------------------------------------------------------
__global__ __launch_bounds__(256) void cvt_tf32_kernel(
    const float* __restrict__ a, float* __restrict__ o, int n)
{
    int i = blockIdx.x * 256 + threadIdx.x;
    if (i < n) o[i] = cvt_tf32(a[i]);
}
__global__ __launch_bounds__(256) void cvt_tf32_v4_kernel(
    const float4* __restrict__ a, float4* __restrict__ o, int n4)
{
    int i = blockIdx.x * 256 + threadIdx.x;
    if (i < n4) {
        float4 v = a[i];
        v.x = cvt_tf32(v.x); v.y = cvt_tf32(v.y);
        v.z = cvt_tf32(v.z); v.w = cvt_tf32(v.w);
        o[i] = v;
    }
}

// ---------------------------------------------------------------------------
// PSP adaptive max pool (separable: per-row segment maxes, then row-range max)
// ---------------------------------------------------------------------------
__global__ __launch_bounds__(128) void psp_kernel(
    const float* __restrict__ in, float* __restrict__ out, int C, int transposed)
{
    __shared__ __align__(16) float sp[4096];
    __shared__ float rm[17][64];
    __shared__ float s8v[64];
    const int bc = blockIdx.x;
    const int b = bc / C, c = bc - b * C;
    const int tid = threadIdx.x;
    const float* plane = in + (size_t)bc * 4096;
    for (int i = tid; i < 1024; i += 128)
        ((float4*)sp)[i] = ((const float4*)plane)[i];
    __syncthreads();

    const int cs[17] = {0,21,42, 0,10,21,32,42,53, 0,8,16,24,32,40,48,56};
    const int ce[17] = {22,43,64, 11,22,32,43,54,64, 8,16,24,32,40,48,56,64};
    for (int idx = tid; idx < 17 * 64; idx += 128) {
        int seg = idx >> 6, row = idx & 63;
        const float* rp = sp + row * 64;
        float m = -3.402823e38f;
        for (int cc = cs[seg]; cc < ce[seg]; ++cc) m = fmaxf(m, rp[cc]);
        rm[seg][row] = m;
    }
    __syncthreads();

    float m = -3.402823e38f;
    int cell = -1;
    if (tid < 64) {                        // s=8
        int i = tid >> 3, j = tid & 7;
        for (int r = i * 8; r < i * 8 + 8; ++r) m = fmaxf(m, rm[9 + j][r]);
        s8v[tid] = m; cell = 46 + tid;
    } else if (tid < 100) {                // s=6
        const int st[6] = {0,10,21,32,42,53}, en[6] = {11,22,32,43,54,64};
        int t = tid - 64, i = t / 6, j = t - i * 6;
        for (int r = st[i]; r < en[i]; ++r) m = fmaxf(m, rm[3 + j][r]);
        cell = 10 + t;
    } else if (tid < 109) {                // s=3
        const int st[3] = {0,21,42}, en[3] = {22,43,64};
        int t = tid - 100, i = t / 3, j = t - i * 3;
        for (int r = st[i]; r < en[i]; ++r) m = fmaxf(m, rm[j][r]);
        cell = 1 + t;
    }
    if (cell >= 0) {
        size_t o = transposed ? ((size_t)b * SS * C + (size_t)cell * C + c)
                              : ((size_t)bc * SS + cell);
        out[o] = m;
    }
    __syncthreads();
    if (tid == 0) {
        float mm = s8v[0];
        for (int i = 1; i < 64; ++i) mm = fmaxf(mm, s8v[i]);
        size_t o = transposed ? ((size_t)b * SS * C + c) : ((size_t)bc * SS);
        out[o] = mm;
    }
}

// ---------------------------------------------------------------------------
// scores = softmax( (qk[b]^T @ key[b]) / 16 )  -> g_p [b][s][n]
// ---------------------------------------------------------------------------
#define SM_KEY 0
#define SM_Q   (CK*SS)
#define SM_S   (CK*SS + CK*64)
#define SMEM_ATTN ((CK*SS + CK*64 + 64*112) * 4)

__global__ __launch_bounds__(256) void attn_scores_kernel(
    const float* __restrict__ qk, const float* __restrict__ key, float* __restrict__ p)
{
    extern __shared__ __align__(16) float sm[];
    float* sKey = sm + SM_KEY;
    float* sQ   = sm + SM_Q;
    float* sS   = sm + SM_S;

    const int b = blockIdx.y, n0 = blockIdx.x * 64;
    const int tid = threadIdx.x;

    const float* kb = key + (size_t)b * CK * SS;
    for (int i = tid; i < (CK * SS) / 4; i += 256)
        ((float4*)sKey)[i] = ((const float4*)kb)[i];

    const float* qb = qk + (size_t)b * CK * HW;
    for (int i = tid; i < CK * 16; i += 256) {
        int c = i >> 4, r4 = i & 15;
        *(float4*)&sQ[c * 64 + r4 * 4] = *(const float4*)&qb[(size_t)c * HW + n0 + r4 * 4];
    }
    __syncthreads();

    const int ty = tid >> 4, tx = tid & 15;
    float acc[4][7];
    #pragma unroll
    for (int i = 0; i < 4; ++i)
        #pragma unroll
        for (int u = 0; u < 7; ++u) acc[i][u] = 0.f;

    for (int c = 0; c < CK; ++c) {
        float4 qv = *(float4*)&sQ[c * 64 + ty * 4];
        float q[4] = {qv.x, qv.y, qv.z, qv.w};
        #pragma unroll
        for (int u = 0; u < 7; ++u) {
            int s = tx + u * 16;
            float kv = sKey[c * SS + s];
            #pragma unroll
            for (int i = 0; i < 4; ++i) acc[i][u] += q[i] * kv;
        }
    }

    #pragma unroll
    for (int u = 0; u < 7; ++u) {
        int s = tx + u * 16;
        if (s < SS) {
            #pragma unroll
            for (int i = 0; i < 4; ++i)
                sS[(ty * 4 + i) * 112 + s] = acc[i][u] * 0.0625f;
        }
    }
    __syncthreads();

    if (tid < 64) {
        float mx = -3.402823e38f;
        for (int s = 0; s < SS; ++s) mx = fmaxf(mx, sS[tid * 112 + s]);
        float sum = 0.f;
        for (int s = 0; s < SS; ++s) {
            float e = __expf(sS[tid * 112 + s] - mx);
            sS[tid * 112 + s] = e; sum += e;
        }
        float inv = 1.f / sum;
        for (int s = 0; s < SS; ++s) sS[tid * 112 + s] *= inv;
    }
    __syncthreads();

    float* pb = p + (size_t)b * SS * HW;
    for (int i = tid; i < SS * 64; i += 256) {
        int s = i >> 6, r = i & 63;
        pb[(size_t)s * HW + n0 + r] = sS[r * 112 + s];
    }
}

// ---------------------------------------------------------------------------
// y[b][c][n] = sum_s P[b][s][n] * value[b][s][c]  (channel-major, tf32-rounded
// so it feeds conv3's B operand directly). 64x64 tile, K=110 in smem.
// ---------------------------------------------------------------------------
__global__ __launch_bounds__(256) void attn_out_kernel(
    const float* __restrict__ p, const float* __restrict__ value, float* __restrict__ y)
{
    __shared__ __align__(16) float sP[SS * 64];
    __shared__ __align__(16) float sV[SS * 64];
    const int b = blockIdx.z, n0 = blockIdx.x * 64, c0 = blockIdx.y * 64;
    const int tid = threadIdx.x;

    const float* pb = p + (size_t)b * SS * HW;
    const float* vb = value + (size_t)b * SS * CV;
    for (int i = tid; i < SS * 16; i += 256) {
        int k = i >> 4, r4 = i & 15;
        *(float4*)&sP[k * 64 + r4 * 4] = *(const float4*)&pb[(size_t)k * HW + n0 + r4 * 4];
        *(float4*)&sV[k * 64 + r4 * 4] = *(const float4*)&vb[(size_t)k * CV + c0 + r4 * 4];
    }
    __syncthreads();

    const int tm = tid >> 4, tn = tid & 15;
    float acc[4][4];
    #pragma unroll
    for (int i = 0; i < 4; ++i)
        #pragma unroll
        for (int j = 0; j < 4; ++j) acc[i][j] = 0.f;

    for (int k = 0; k < SS; ++k) {
        float4 pv = *(float4*)&sP[k * 64 + tm * 4];
        float4 vv = *(float4*)&sV[k * 64 + tn * 4];
        float pa[4] = {pv.x, pv.y, pv.z, pv.w};
        float va[4] = {vv.x, vv.y, vv.z, vv.w};
        #pragma unroll
        for (int i = 0; i < 4; ++i)
            #pragma unroll
            for (int j = 0; j < 4; ++j)
                acc[i][j] += pa[i] * va[j];
    }

    float* yb = y + (size_t)b * CV * HW;
    #pragma unroll
    for (int j = 0; j < 4; ++j) {
        float4 o = make_float4(cvt_tf32(acc[0][j]), cvt_tf32(acc[1][j]),
                               cvt_tf32(acc[2][j]), cvt_tf32(acc[3][j]));
        *(float4*)&yb[(size_t)(c0 + tn * 4 + j) * HW + n0 + tm * 4] = o;
    }
}

// ---------------------------------------------------------------------------
extern "C" void kernel_launch(void* const* d_in, const int* in_sizes, int n_in,
                              void* d_out, int out_size)
{
    const float* x        = (const float*)d_in[0];
    const float* qk_w     = (const float*)d_in[1];
    const float* qk_gamma = (const float*)d_in[2];
    const float* qk_beta  = (const float*)d_in[3];
    const float* qk_mean  = (const float*)d_in[4];
    const float* qk_var   = (const float*)d_in[5];
    const float* v_w      = (const float*)d_in[6];
    const float* v_gamma  = (const float*)d_in[7];
    const float* v_beta   = (const float*)d_in[8];
    const float* v_mean   = (const float*)d_in[9];
    const float* v_var    = (const float*)d_in[10];
    const float* out_w    = (const float*)d_in[11];
    const float* o_gamma  = (const float*)d_in[12];
    const float* o_beta   = (const float*)d_in[13];
    const float* o_mean   = (const float*)d_in[14];
    const float* o_var    = (const float*)d_in[15];
    float* out = (float*)d_out;

    float *qk, *val, *xc, *y, *key, *value, *p, *wq, *wv, *wo;
    cudaGetSymbolAddress((void**)&qk,    g_qk);
    cudaGetSymbolAddress((void**)&val,   g_val);
    cudaGetSymbolAddress((void**)&xc,    g_xc);
    cudaGetSymbolAddress((void**)&y,     g_y);
    cudaGetSymbolAddress((void**)&key,   g_key);
    cudaGetSymbolAddress((void**)&value, g_value);
    cudaGetSymbolAddress((void**)&p,     g_p);
    cudaGetSymbolAddress((void**)&wq,    g_wq);
    cudaGetSymbolAddress((void**)&wv,    g_wv);
    cudaGetSymbolAddress((void**)&wo,    g_wo);

    cudaFuncSetAttribute(conv_mma_kernel<true, false>,
                         cudaFuncAttributeMaxDynamicSharedMemorySize, CONV_SMEM);
    cudaFuncSetAttribute(conv_mma_kernel<false, true>,
                         cudaFuncAttributeMaxDynamicSharedMemorySize, CONV_SMEM);
    cudaFuncSetAttribute(attn_scores_kernel,
                         cudaFuncAttributeMaxDynamicSharedMemorySize, SMEM_ATTN);

    // 0) tf32 pre-rounding: weights + x (keeps [b][k][n] layout)
    cvt_tf32_kernel<<<(CK*CIN + 255) / 256, 256>>>(qk_w, wq, CK*CIN);
    cvt_tf32_kernel<<<(CV*CIN + 255) / 256, 256>>>(v_w,  wv, CV*CIN);
    cvt_tf32_kernel<<<(CIN*CV + 255) / 256, 256>>>(out_w, wo, CIN*CV);
    cvt_tf32_v4_kernel<<<(BB*CIN*HW/4 + 255) / 256, 256>>>(
        (const float4*)x, (float4*)xc, BB*CIN*HW/4);

    // 1) qk = relu(bn(conv(x, qk_w)))   [8,256,4096]
    conv_mma_kernel<true, false><<<dim3(32, CK/128, BB), 256, CONV_SMEM>>>(
        wq, xc, qk_gamma, qk_beta, qk_mean, qk_var, nullptr, qk, CK);
    // 2) val = relu(bn(conv(x, v_w)))   [8,512,4096]
    conv_mma_kernel<true, false><<<dim3(32, CV/128, BB), 256, CONV_SMEM>>>(
        wv, xc, v_gamma, v_beta, v_mean, v_var, nullptr, val, CV);
    // 3) key = psp(qk); value = psp(val)^T
    psp_kernel<<<BB * CK, 128>>>(qk,  key,   CK, 0);
    psp_kernel<<<BB * CV, 128>>>(val, value, CV, 1);
    // 4) P = softmax(q @ key / 16)
    attn_scores_kernel<<<dim3(64, BB), 256, SMEM_ATTN>>>(qk, key, p);
    // 5) y[c][n] = sum_s P[s][n] * value[s][c]  (tf32-rounded)
    attn_out_kernel<<<dim3(64, CV/64, BB), 256>>>(p, value, y);
    // 6) out = x + bn(conv(y, out_w))
    conv_mma_kernel<false, true><<<dim3(32, CIN/128, BB), 256, CONV_SMEM>>>(
        wo, y, o_gamma, o_beta, o_mean, o_var, x, out, CIN);
}

// round 4
// speedup vs baseline: 1.8798x; 1.1343x over previous
#include <cuda_runtime.h>
#include <cuda_fp16.h>
#include <cstdint>
#include <math.h>

#define BB   8
#define CIN  512
#define CK   256
#define CV   512
#define HW   4096
#define SS   110

// Scratch (allocation-free rule: __device__ globals)
__device__ __align__(16) float  g_qk   [BB*CK*HW];   // [b][c][n] fp32
__device__ __align__(16) float  g_val  [BB*CV*HW];   // [b][c][n] fp32
__device__ __align__(16) __half g_xh   [BB*CIN*HW];  // [b][k][n] fp16
__device__ __align__(16) __half g_yh   [BB*CV*HW];   // [b][c][n] fp16
__device__ __align__(16) float  g_key  [BB*CK*SS];   // [b][c][s]
__device__ __align__(16) float  g_value[BB*SS*CV];   // [b][s][c]
__device__ __align__(16) float  g_p    [BB*SS*HW];   // [b][s][n]
__device__ __align__(16) __half g_wq   [CK*CIN];
__device__ __align__(16) __half g_wv   [CV*CIN];
__device__ __align__(16) __half g_wo   [CIN*CV];

// ---------------------------------------------------------------------------
__device__ __forceinline__ uint32_t smem_u32(const void* p) {
    uint32_t a;
    asm("{ .reg .u64 t; cvta.to.shared.u64 t, %1; cvt.u32.u64 %0, t; }" : "=r"(a) : "l"(p));
    return a;
}
__device__ __forceinline__ void ldsm_x4(uint32_t* r, uint32_t addr) {
    asm volatile("ldmatrix.sync.aligned.m8n8.x4.shared.b16 {%0,%1,%2,%3}, [%4];"
        : "=r"(r[0]), "=r"(r[1]), "=r"(r[2]), "=r"(r[3]) : "r"(addr));
}
__device__ __forceinline__ void ldsm_x4_t(uint32_t* r, uint32_t addr) {
    asm volatile("ldmatrix.sync.aligned.m8n8.x4.trans.shared.b16 {%0,%1,%2,%3}, [%4];"
        : "=r"(r[0]), "=r"(r[1]), "=r"(r[2]), "=r"(r[3]) : "r"(addr));
}
__device__ __forceinline__ void mma_f16(float* c, const uint32_t* a, const uint32_t* b) {
    asm volatile(
        "mma.sync.aligned.m16n8k16.row.col.f32.f16.f16.f32 "
        "{%0,%1,%2,%3}, {%4,%5,%6,%7}, {%8,%9}, {%0,%1,%2,%3};"
        : "+f"(c[0]), "+f"(c[1]), "+f"(c[2]), "+f"(c[3])
        : "r"(a[0]), "r"(a[1]), "r"(a[2]), "r"(a[3]), "r"(b[0]), "r"(b[1]));
}

// ---------------------------------------------------------------------------
// conv1x1 + BN (+ReLU)(+residual) via fp16 mma.sync m16n8k16 + ldmatrix.
// out[b,m,n] = act( s[m]*sum_k W[m,k]*X[b,k,n] + t[m] ) (+ resid)
// CTA: 128m x 128n, 8 warps (2m x 4n), warp tile 64m x 32n.
// K staged 64 at a time, double-buffered cp.async.
// smem A: [m][k] halves, stride 72;  smem B: [k][n] halves, stride 136.
// Both strides give conflict-free 8-row ldmatrix phases (banks 4r mod 32).
// ---------------------------------------------------------------------------
#define A_STRH 72
#define B_STRH 136
#define A_TILE_B (128*A_STRH*2)            // 18432
#define B_TILE_B (64*B_STRH*2)             // 17408
#define STAGE_B  (A_TILE_B + B_TILE_B)     // 35840
#define CONV_SMEM (2*STAGE_B)              // 71680

template<bool RELU, bool RESID>
__global__ __launch_bounds__(256) void conv_mma_kernel(
    const __half* __restrict__ W, const __half* __restrict__ X,
    const float* __restrict__ gamma, const float* __restrict__ beta,
    const float* __restrict__ mean,  const float* __restrict__ var,
    const float* __restrict__ resid, float* __restrict__ out, int M)
{
    extern __shared__ __align__(16) char smc[];
    const uint32_t sb = smem_u32(smc);
    const int tid = threadIdx.x;
    const int lane = tid & 31;
    const int wid  = tid >> 5;
    const int gidr = lane >> 2, t4 = lane & 3;
    const int wm = wid >> 2, wn = wid & 3;            // 2 x 4 warp grid
    const int n0 = blockIdx.x * 128, m0 = blockIdx.y * 128, b = blockIdx.z;

    const __half* gW = W + (size_t)m0 * CIN;
    const __half* gX = X + (size_t)b * CIN * HW + n0;

    auto load_stage = [&](int s) {
        const uint32_t base = sb + (uint32_t)(s & 1) * STAGE_B;
        const __half* ga = gW + s * 64;
        const __half* gb = gX + (size_t)s * 64 * HW;
        #pragma unroll
        for (int i = 0; i < 4; ++i) {               // A: 128 rows x 8 chunks
            int idx = i * 256 + tid;
            int r = idx >> 3, c = idx & 7;
            asm volatile("cp.async.cg.shared.global [%0], [%1], 16;"
                :: "r"(base + (uint32_t)(r * A_STRH + c * 8) * 2),
                   "l"(ga + (size_t)r * CIN + c * 8));
        }
        #pragma unroll
        for (int i = 0; i < 4; ++i) {               // B: 64 rows x 16 chunks
            int idx = i * 256 + tid;
            int r = idx >> 4, c = idx & 15;
            asm volatile("cp.async.cg.shared.global [%0], [%1], 16;"
                :: "r"(base + A_TILE_B + (uint32_t)(r * B_STRH + c * 8) * 2),
                   "l"(gb + (size_t)r * HW + c * 8));
        }
        asm volatile("cp.async.commit_group;" ::: "memory");
    };

    float acc[4][4][4];
    #pragma unroll
    for (int mt = 0; mt < 4; ++mt)
        #pragma unroll
        for (int nt = 0; nt < 4; ++nt)
            #pragma unroll
            for (int r = 0; r < 4; ++r) acc[mt][nt][r] = 0.f;

    load_stage(0);

    // Per-thread ldmatrix address components
    const int a_row = (lane & 15);                   // within m16 tile
    const int a_koff = (lane >> 4) * 8;
    const int b_krow = ((lane >> 3) & 1) * 8 + (lane & 7);
    const int b_noff = (lane >> 4) * 8;

    for (int kt = 0; kt < 8; ++kt) {
        if (kt + 1 < 8) {
            load_stage(kt + 1);
            asm volatile("cp.async.wait_group 1;" ::: "memory");
        } else {
            asm volatile("cp.async.wait_group 0;" ::: "memory");
        }
        __syncthreads();

        const uint32_t sA = sb + (uint32_t)(kt & 1) * STAGE_B;
        const uint32_t sB = sA + A_TILE_B;
        #pragma unroll
        for (int s16 = 0; s16 < 4; ++s16) {
            const int kk = s16 * 16;
            uint32_t af[4][4], bf[4][2];
            #pragma unroll
            for (int mt = 0; mt < 4; ++mt) {
                int row = wm * 64 + mt * 16 + a_row;
                ldsm_x4(af[mt], sA + (uint32_t)(row * A_STRH + kk + a_koff) * 2);
            }
            #pragma unroll
            for (int nt2 = 0; nt2 < 2; ++nt2) {
                uint32_t r4[4];
                int ncol = wn * 32 + nt2 * 16 + b_noff;
                ldsm_x4_t(r4, sB + (uint32_t)((kk + b_krow) * B_STRH + ncol) * 2);
                bf[nt2*2][0] = r4[0]; bf[nt2*2][1] = r4[1];
                bf[nt2*2+1][0] = r4[2]; bf[nt2*2+1][1] = r4[3];
            }
            #pragma unroll
            for (int mt = 0; mt < 4; ++mt)
                #pragma unroll
                for (int nt = 0; nt < 4; ++nt)
                    mma_f16(acc[mt][nt], af[mt], bf[nt]);
        }
        __syncthreads();
    }

    // Epilogue: BN (+ReLU) (+residual)
    const size_t bo = (size_t)b * M * HW;
    #pragma unroll
    for (int mt = 0; mt < 4; ++mt) {
        const int ml = m0 + wm * 64 + mt * 16 + gidr;
        const int mh = ml + 8;
        const float scl = gamma[ml] * rsqrtf(var[ml] + 1e-5f);
        const float ttl = beta[ml] - mean[ml] * scl;
        const float sch = gamma[mh] * rsqrtf(var[mh] + 1e-5f);
        const float tth = beta[mh] - mean[mh] * sch;
        #pragma unroll
        for (int nt = 0; nt < 4; ++nt) {
            const int nn = n0 + wn * 32 + nt * 8 + 2 * t4;
            float2 vl, vh;
            vl.x = acc[mt][nt][0] * scl + ttl;
            vl.y = acc[mt][nt][1] * scl + ttl;
            vh.x = acc[mt][nt][2] * sch + tth;
            vh.y = acc[mt][nt][3] * sch + tth;
            if (RELU) {
                vl.x = fmaxf(vl.x, 0.f); vl.y = fmaxf(vl.y, 0.f);
                vh.x = fmaxf(vh.x, 0.f); vh.y = fmaxf(vh.y, 0.f);
            }
            if (RESID) {
                float2 rl = *(const float2*)(resid + bo + (size_t)ml * HW + nn);
                float2 rh = *(const float2*)(resid + bo + (size_t)mh * HW + nn);
                vl.x += rl.x; vl.y += rl.y; vh.x += rh.x; vh.y += rh.y;
            }
            *(float2*)(out + bo + (size_t)ml * HW + nn) = vl;
            *(float2*)(out + bo + (size_t)mh * HW + nn) = vh;
        }
    }
}

// ---------------------------------------------------------------------------
// fp32 -> fp16 conversion
// ---------------------------------------------------------------------------
__global__ __launch_bounds__(256) void cvt_half_kernel(
    const float* __restrict__ a, __half* __restrict__ o, int n)
{
    int i = blockIdx.x * 256 + threadIdx.x;
    if (i < n) o[i] = __float2half_rn(a[i]);
}
__global__ __launch_bounds__(256) void cvt_half_v8_kernel(
    const float4* __restrict__ a, uint4* __restrict__ o, int n8)
{
    int i = blockIdx.x * 256 + threadIdx.x;
    if (i < n8) {
        float4 f0 = a[2*i], f1 = a[2*i+1];
        __half2 h0 = __floats2half2_rn(f0.x, f0.y);
        __half2 h1 = __floats2half2_rn(f0.z, f0.w);
        __half2 h2 = __floats2half2_rn(f1.x, f1.y);
        __half2 h3 = __floats2half2_rn(f1.z, f1.w);
        uint4 u;
        u.x = *(uint32_t*)&h0; u.y = *(uint32_t*)&h1;
        u.z = *(uint32_t*)&h2; u.w = *(uint32_t*)&h3;
        o[i] = u;
    }
}

// ---------------------------------------------------------------------------
// PSP adaptive max pool (separable)
// ---------------------------------------------------------------------------
__global__ __launch_bounds__(128) void psp_kernel(
    const float* __restrict__ in, float* __restrict__ out, int C, int transposed)
{
    __shared__ __align__(16) float sp[4096];
    __shared__ float rm[17][64];
    __shared__ float s8v[64];
    const int bc = blockIdx.x;
    const int b = bc / C, c = bc - b * C;
    const int tid = threadIdx.x;
    const float* plane = in + (size_t)bc * 4096;
    for (int i = tid; i < 1024; i += 128)
        ((float4*)sp)[i] = ((const float4*)plane)[i];
    __syncthreads();

    const int cs[17] = {0,21,42, 0,10,21,32,42,53, 0,8,16,24,32,40,48,56};
    const int ce[17] = {22,43,64, 11,22,32,43,54,64, 8,16,24,32,40,48,56,64};
    for (int idx = tid; idx < 17 * 64; idx += 128) {
        int seg = idx >> 6, row = idx & 63;
        const float* rp = sp + row * 64;
        float m = -3.402823e38f;
        for (int cc = cs[seg]; cc < ce[seg]; ++cc) m = fmaxf(m, rp[cc]);
        rm[seg][row] = m;
    }
    __syncthreads();

    float m = -3.402823e38f;
    int cell = -1;
    if (tid < 64) {                        // s=8
        int i = tid >> 3, j = tid & 7;
        for (int r = i * 8; r < i * 8 + 8; ++r) m = fmaxf(m, rm[9 + j][r]);
        s8v[tid] = m; cell = 46 + tid;
    } else if (tid < 100) {                // s=6
        const int st[6] = {0,10,21,32,42,53}, en[6] = {11,22,32,43,54,64};
        int t = tid - 64, i = t / 6, j = t - i * 6;
        for (int r = st[i]; r < en[i]; ++r) m = fmaxf(m, rm[3 + j][r]);
        cell = 10 + t;
    } else if (tid < 109) {                // s=3
        const int st[3] = {0,21,42}, en[3] = {22,43,64};
        int t = tid - 100, i = t / 3, j = t - i * 3;
        for (int r = st[i]; r < en[i]; ++r) m = fmaxf(m, rm[j][r]);
        cell = 1 + t;
    }
    if (cell >= 0) {
        size_t o = transposed ? ((size_t)b * SS * C + (size_t)cell * C + c)
                              : ((size_t)bc * SS + cell);
        out[o] = m;
    }
    __syncthreads();
    if (tid == 0) {
        float mm = s8v[0];
        for (int i = 1; i < 64; ++i) mm = fmaxf(mm, s8v[i]);
        size_t o = transposed ? ((size_t)b * SS * C + c) : ((size_t)bc * SS);
        out[o] = mm;
    }
}

// ---------------------------------------------------------------------------
// scores = softmax( (qk[b]^T @ key[b]) / 16 )  -> g_p [b][s][n]
// ---------------------------------------------------------------------------
#define SM_KEY 0
#define SM_Q   (CK*SS)
#define SM_S   (CK*SS + CK*64)
#define SMEM_ATTN ((CK*SS + CK*64 + 64*112) * 4)

__global__ __launch_bounds__(256) void attn_scores_kernel(
    const float* __restrict__ qk, const float* __restrict__ key, float* __restrict__ p)
{
    extern __shared__ __align__(16) float sm[];
    float* sKey = sm + SM_KEY;
    float* sQ   = sm + SM_Q;
    float* sS   = sm + SM_S;

    const int b = blockIdx.y, n0 = blockIdx.x * 64;
    const int tid = threadIdx.x;

    const float* kb = key + (size_t)b * CK * SS;
    for (int i = tid; i < (CK * SS) / 4; i += 256)
        ((float4*)sKey)[i] = ((const float4*)kb)[i];

    const float* qb = qk + (size_t)b * CK * HW;
    for (int i = tid; i < CK * 16; i += 256) {
        int c = i >> 4, r4 = i & 15;
        *(float4*)&sQ[c * 64 + r4 * 4] = *(const float4*)&qb[(size_t)c * HW + n0 + r4 * 4];
    }
    __syncthreads();

    const int ty = tid >> 4, tx = tid & 15;
    float acc[4][7];
    #pragma unroll
    for (int i = 0; i < 4; ++i)
        #pragma unroll
        for (int u = 0; u < 7; ++u) acc[i][u] = 0.f;

    for (int c = 0; c < CK; ++c) {
        float4 qv = *(float4*)&sQ[c * 64 + ty * 4];
        float q[4] = {qv.x, qv.y, qv.z, qv.w};
        #pragma unroll
        for (int u = 0; u < 7; ++u) {
            int s = tx + u * 16;
            float kv = sKey[c * SS + s];
            #pragma unroll
            for (int i = 0; i < 4; ++i) acc[i][u] += q[i] * kv;
        }
    }

    #pragma unroll
    for (int u = 0; u < 7; ++u) {
        int s = tx + u * 16;
        if (s < SS) {
            #pragma unroll
            for (int i = 0; i < 4; ++i)
                sS[(ty * 4 + i) * 112 + s] = acc[i][u] * 0.0625f;
        }
    }
    __syncthreads();

    if (tid < 64) {
        float mx = -3.402823e38f;
        for (int s = 0; s < SS; ++s) mx = fmaxf(mx, sS[tid * 112 + s]);
        float sum = 0.f;
        for (int s = 0; s < SS; ++s) {
            float e = __expf(sS[tid * 112 + s] - mx);
            sS[tid * 112 + s] = e; sum += e;
        }
        float inv = 1.f / sum;
        for (int s = 0; s < SS; ++s) sS[tid * 112 + s] *= inv;
    }
    __syncthreads();

    float* pb = p + (size_t)b * SS * HW;
    for (int i = tid; i < SS * 64; i += 256) {
        int s = i >> 6, r = i & 63;
        pb[(size_t)s * HW + n0 + r] = sS[r * 112 + s];
    }
}

// ---------------------------------------------------------------------------
// y[b][c][n] = sum_s P[b][s][n] * value[b][s][c], emitted as fp16 [c][n]
// (direct B operand for conv3). 64x64 tile, K=110 in smem.
// ---------------------------------------------------------------------------
__global__ __launch_bounds__(256) void attn_out_kernel(
    const float* __restrict__ p, const float* __restrict__ value, __half* __restrict__ y)
{
    __shared__ __align__(16) float sP[SS * 64];
    __shared__ __align__(16) float sV[SS * 64];
    const int b = blockIdx.z, n0 = blockIdx.x * 64, c0 = blockIdx.y * 64;
    const int tid = threadIdx.x;

    const float* pb = p + (size_t)b * SS * HW;
    const float* vb = value + (size_t)b * SS * CV;
    for (int i = tid; i < SS * 16; i += 256) {
        int k = i >> 4, r4 = i & 15;
        *(float4*)&sP[k * 64 + r4 * 4] = *(const float4*)&pb[(size_t)k * HW + n0 + r4 * 4];
        *(float4*)&sV[k * 64 + r4 * 4] = *(const float4*)&vb[(size_t)k * CV + c0 + r4 * 4];
    }
    __syncthreads();

    const int tm = tid >> 4, tn = tid & 15;
    float acc[4][4];
    #pragma unroll
    for (int i = 0; i < 4; ++i)
        #pragma unroll
        for (int j = 0; j < 4; ++j) acc[i][j] = 0.f;

    for (int k = 0; k < SS; ++k) {
        float4 pv = *(float4*)&sP[k * 64 + tm * 4];
        float4 vv = *(float4*)&sV[k * 64 + tn * 4];
        float pa[4] = {pv.x, pv.y, pv.z, pv.w};
        float va[4] = {vv.x, vv.y, vv.z, vv.w};
        #pragma unroll
        for (int i = 0; i < 4; ++i)
            #pragma unroll
            for (int j = 0; j < 4; ++j)
                acc[i][j] += pa[i] * va[j];
    }

    __half* yb = y + (size_t)b * CV * HW;
    #pragma unroll
    for (int j = 0; j < 4; ++j) {
        __half2 h0 = __floats2half2_rn(acc[0][j], acc[1][j]);
        __half2 h1 = __floats2half2_rn(acc[2][j], acc[3][j]);
        uint2 u; u.x = *(uint32_t*)&h0; u.y = *(uint32_t*)&h1;
        *(uint2*)&yb[(size_t)(c0 + tn * 4 + j) * HW + n0 + tm * 4] = u;
    }
}

// ---------------------------------------------------------------------------
extern "C" void kernel_launch(void* const* d_in, const int* in_sizes, int n_in,
                              void* d_out, int out_size)
{
    const float* x        = (const float*)d_in[0];
    const float* qk_w     = (const float*)d_in[1];
    const float* qk_gamma = (const float*)d_in[2];
    const float* qk_beta  = (const float*)d_in[3];
    const float* qk_mean  = (const float*)d_in[4];
    const float* qk_var   = (const float*)d_in[5];
    const float* v_w      = (const float*)d_in[6];
    const float* v_gamma  = (const float*)d_in[7];
    const float* v_beta   = (const float*)d_in[8];
    const float* v_mean   = (const float*)d_in[9];
    const float* v_var    = (const float*)d_in[10];
    const float* out_w    = (const float*)d_in[11];
    const float* o_gamma  = (const float*)d_in[12];
    const float* o_beta   = (const float*)d_in[13];
    const float* o_mean   = (const float*)d_in[14];
    const float* o_var    = (const float*)d_in[15];
    float* out = (float*)d_out;

    float *qk, *val, *key, *value, *p;
    __half *xh, *yh, *wq, *wv, *wo;
    cudaGetSymbolAddress((void**)&qk,    g_qk);
    cudaGetSymbolAddress((void**)&val,   g_val);
    cudaGetSymbolAddress((void**)&xh,    g_xh);
    cudaGetSymbolAddress((void**)&yh,    g_yh);
    cudaGetSymbolAddress((void**)&key,   g_key);
    cudaGetSymbolAddress((void**)&value, g_value);
    cudaGetSymbolAddress((void**)&p,     g_p);
    cudaGetSymbolAddress((void**)&wq,    g_wq);
    cudaGetSymbolAddress((void**)&wv,    g_wv);
    cudaGetSymbolAddress((void**)&wo,    g_wo);

    cudaFuncSetAttribute(conv_mma_kernel<true, false>,
                         cudaFuncAttributeMaxDynamicSharedMemorySize, CONV_SMEM);
    cudaFuncSetAttribute(conv_mma_kernel<false, true>,
                         cudaFuncAttributeMaxDynamicSharedMemorySize, CONV_SMEM);
    cudaFuncSetAttribute(attn_scores_kernel,
                         cudaFuncAttributeMaxDynamicSharedMemorySize, SMEM_ATTN);

    // 0) fp16 conversion: weights + x
    cvt_half_kernel<<<(CK*CIN + 255) / 256, 256>>>(qk_w, wq, CK*CIN);
    cvt_half_kernel<<<(CV*CIN + 255) / 256, 256>>>(v_w,  wv, CV*CIN);
    cvt_half_kernel<<<(CIN*CV + 255) / 256, 256>>>(out_w, wo, CIN*CV);
    cvt_half_v8_kernel<<<(BB*CIN*HW/8 + 255) / 256, 256>>>(
        (const float4*)x, (uint4*)xh, BB*CIN*HW/8);

    // 1) qk = relu(bn(conv(x, qk_w)))   [8,256,4096]
    conv_mma_kernel<true, false><<<dim3(32, CK/128, BB), 256, CONV_SMEM>>>(
        wq, xh, qk_gamma, qk_beta, qk_mean, qk_var, nullptr, qk, CK);
    // 2) val = relu(bn(conv(x, v_w)))   [8,512,4096]
    conv_mma_kernel<true, false><<<dim3(32, CV/128, BB), 256, CONV_SMEM>>>(
        wv, xh, v_gamma, v_beta, v_mean, v_var, nullptr, val, CV);
    // 3) key = psp(qk); value = psp(val)^T
    psp_kernel<<<BB * CK, 128>>>(qk,  key,   CK, 0);
    psp_kernel<<<BB * CV, 128>>>(val, value, CV, 1);
    // 4) P = softmax(q @ key / 16)
    attn_scores_kernel<<<dim3(64, BB), 256, SMEM_ATTN>>>(qk, key, p);
    // 5) y[c][n] = sum_s P[s][n] * value[s][c]  (fp16 out)
    attn_out_kernel<<<dim3(64, CV/64, BB), 256>>>(p, value, yh);
    // 6) out = x + bn(conv(y, out_w))
    conv_mma_kernel<false, true><<<dim3(32, CIN/128, BB), 256, CONV_SMEM>>>(
        wo, yh, o_gamma, o_beta, o_mean, o_var, x, out, CIN);
}

// round 5
// speedup vs baseline: 2.6611x; 1.4156x over previous
#include <cuda_runtime.h>
#include <cuda_fp16.h>
#include <cstdint>
#include <math.h>

#define BB   8
#define CIN  512
#define CK   256
#define CV   512
#define HW   4096
#define SS   110

// Scratch (__device__ globals are zero-initialized at module load; pad regions
// below are never written and thus stay zero -> free zero-padding).
__device__ __align__(16) __half g_xh    [BB*CIN*HW];    // [b][k][n]
__device__ __align__(16) __half g_qkh   [BB*CK*HW];     // [b][c][n]
__device__ __align__(16) __half g_valh  [BB*CV*HW];     // [b][c][n]
__device__ __align__(16) __half g_keyh  [BB*128*CK];    // [b][s(pad128)][c]
__device__ __align__(16) __half g_vpsp  [BB*CV*112];    // [b][c][s(pad112)]
__device__ __align__(16) __half g_sh    [BB*128*HW];    // [b][s(pad128)][n] raw scores
__device__ __align__(16) __half g_ph    [BB*112*HW];    // [b][s(pad112)][n] softmax
__device__ __align__(16) __half g_yh    [BB*CV*HW];     // [b][c][n]
__device__ __align__(16) __half g_wq    [CK*CIN];
__device__ __align__(16) __half g_wv    [CV*CIN];
__device__ __align__(16) __half g_wo    [CIN*CV];

// ---------------------------------------------------------------------------
__device__ __forceinline__ uint32_t smem_u32(const void* p) {
    uint32_t a;
    asm("{ .reg .u64 t; cvta.to.shared.u64 t, %1; cvt.u32.u64 %0, t; }" : "=r"(a) : "l"(p));
    return a;
}
__device__ __forceinline__ void ldsm_x4(uint32_t* r, uint32_t addr) {
    asm volatile("ldmatrix.sync.aligned.m8n8.x4.shared.b16 {%0,%1,%2,%3}, [%4];"
        : "=r"(r[0]), "=r"(r[1]), "=r"(r[2]), "=r"(r[3]) : "r"(addr));
}
__device__ __forceinline__ void ldsm_x4_t(uint32_t* r, uint32_t addr) {
    asm volatile("ldmatrix.sync.aligned.m8n8.x4.trans.shared.b16 {%0,%1,%2,%3}, [%4];"
        : "=r"(r[0]), "=r"(r[1]), "=r"(r[2]), "=r"(r[3]) : "r"(addr));
}
__device__ __forceinline__ void mma_f16(float* c, const uint32_t* a, const uint32_t* b) {
    asm volatile(
        "mma.sync.aligned.m16n8k16.row.col.f32.f16.f16.f32 "
        "{%0,%1,%2,%3}, {%4,%5,%6,%7}, {%8,%9}, {%0,%1,%2,%3};"
        : "+f"(c[0]), "+f"(c[1]), "+f"(c[2]), "+f"(c[3])
        : "r"(a[0]), "r"(a[1]), "r"(a[2]), "r"(a[3]), "r"(b[0]), "r"(b[1]));
}
__device__ __forceinline__ void cpa16(uint32_t dst, const void* src) {
    asm volatile("cp.async.cg.shared.global [%0], [%1], 16;" :: "r"(dst), "l"(src));
}

// ---------------------------------------------------------------------------
// Generalized GEMM: out[b,m,n] = epi( sum_k A[m,k] * B[b,k,n] )
// A row-major [M,Ktot] (lda=Ktot, + a_bstride per batch), B [Ktot,4096].
// CTA 128m x 128n, 8 warps (2x4), warp 64x32. K staged 32, 4-stage pipeline.
// ---------------------------------------------------------------------------
#define A_STRH 40
#define B_STRH 136
#define A_STG  (128*A_STRH*2)              // 10240 B
#define B_STG  (32*B_STRH*2)               // 8704 B
#define STG    (A_STG + B_STG)             // 18944 B
#define NSTAGE 4
#define GEMM_SMEM (NSTAGE*STG)             // 75776 B

template<bool BN, bool RELU, bool RESID, bool HALF_OUT>
__global__ __launch_bounds__(256) void gemm_kernel(
    const __half* __restrict__ A, size_t a_bstride,
    const __half* __restrict__ Bm, size_t b_bstride,
    const float* __restrict__ gamma, const float* __restrict__ beta,
    const float* __restrict__ mean,  const float* __restrict__ var,
    float uscale,
    const float* __restrict__ resid,
    void* __restrict__ outp, size_t o_bstride,
    int Ktot)
{
    extern __shared__ __align__(16) char smc[];
    const uint32_t sb = smem_u32(smc);
    const int tid = threadIdx.x, lane = tid & 31, wid = tid >> 5;
    const int gidr = lane >> 2, t4 = lane & 3;
    const int wm = wid >> 2, wn = wid & 3;
    const int n0 = blockIdx.x * 128, m0 = blockIdx.y * 128, b = blockIdx.z;
    const int NK = Ktot >> 5;

    const __half* gA = A + (size_t)b * a_bstride + (size_t)m0 * Ktot;
    const __half* gB = Bm + (size_t)b * b_bstride + n0;

    auto load_stage = [&](int s) {
        const uint32_t base = sb + (uint32_t)(s & (NSTAGE-1)) * STG;
        #pragma unroll
        for (int it = 0; it < 2; ++it) {            // A: 128r x 4 chunks
            int idx = it * 256 + tid;
            int r = idx >> 2, c = idx & 3;
            cpa16(base + (uint32_t)(r * A_STRH + c * 8) * 2,
                  gA + (size_t)r * Ktot + s * 32 + c * 8);
        }
        #pragma unroll
        for (int it = 0; it < 2; ++it) {            // B: 32r x 16 chunks
            int idx = it * 256 + tid;
            int r = idx >> 4, c = idx & 15;
            cpa16(base + A_STG + (uint32_t)(r * B_STRH + c * 8) * 2,
                  gB + (size_t)(s * 32 + r) * HW + c * 8);
        }
        asm volatile("cp.async.commit_group;" ::: "memory");
    };

    float acc[4][4][4];
    #pragma unroll
    for (int mt = 0; mt < 4; ++mt)
        #pragma unroll
        for (int nt = 0; nt < 4; ++nt)
            #pragma unroll
            for (int r = 0; r < 4; ++r) acc[mt][nt][r] = 0.f;

    // prologue: stages 0..NSTAGE-2
    for (int s = 0; s < NSTAGE - 1 && s < NK; ++s) load_stage(s);
    asm volatile("cp.async.wait_group 2;" ::: "memory");
    __syncthreads();

    const int a_row = lane & 15, a_koff = (lane >> 4) * 8;
    const int b_krow = ((lane >> 3) & 1) * 8 + (lane & 7);
    const int b_noff = (lane >> 4) * 8;

    for (int kt = 0; kt < NK; ++kt) {
        if (kt + NSTAGE - 1 < NK) load_stage(kt + NSTAGE - 1);
        else asm volatile("cp.async.commit_group;" ::: "memory");

        const uint32_t sA = sb + (uint32_t)(kt & (NSTAGE-1)) * STG;
        const uint32_t sB = sA + A_STG;
        #pragma unroll
        for (int s16 = 0; s16 < 2; ++s16) {
            const int kk = s16 * 16;
            uint32_t af[4][4], bf[4][2];
            #pragma unroll
            for (int mt = 0; mt < 4; ++mt) {
                int row = wm * 64 + mt * 16 + a_row;
                ldsm_x4(af[mt], sA + (uint32_t)(row * A_STRH + kk + a_koff) * 2);
            }
            #pragma unroll
            for (int nt2 = 0; nt2 < 2; ++nt2) {
                uint32_t r4[4];
                int ncol = wn * 32 + nt2 * 16 + b_noff;
                ldsm_x4_t(r4, sB + (uint32_t)((kk + b_krow) * B_STRH + ncol) * 2);
                bf[nt2*2][0] = r4[0]; bf[nt2*2][1] = r4[1];
                bf[nt2*2+1][0] = r4[2]; bf[nt2*2+1][1] = r4[3];
            }
            #pragma unroll
            for (int mt = 0; mt < 4; ++mt)
                #pragma unroll
                for (int nt = 0; nt < 4; ++nt)
                    mma_f16(acc[mt][nt], af[mt], bf[nt]);
        }
        asm volatile("cp.async.wait_group 2;" ::: "memory");
        __syncthreads();
    }

    // Epilogue
    #pragma unroll
    for (int mt = 0; mt < 4; ++mt) {
        const int ml = m0 + wm * 64 + mt * 16 + gidr;
        const int mh = ml + 8;
        float scl, ttl, sch, tth;
        if (BN) {
            scl = gamma[ml] * rsqrtf(var[ml] + 1e-5f);
            ttl = beta[ml] - mean[ml] * scl;
            sch = gamma[mh] * rsqrtf(var[mh] + 1e-5f);
            tth = beta[mh] - mean[mh] * sch;
        } else { scl = uscale; ttl = 0.f; sch = uscale; tth = 0.f; }
        #pragma unroll
        for (int nt = 0; nt < 4; ++nt) {
            const int nn = n0 + wn * 32 + nt * 8 + 2 * t4;
            float2 vl, vh;
            vl.x = acc[mt][nt][0] * scl + ttl;
            vl.y = acc[mt][nt][1] * scl + ttl;
            vh.x = acc[mt][nt][2] * sch + tth;
            vh.y = acc[mt][nt][3] * sch + tth;
            if (RELU) {
                vl.x = fmaxf(vl.x, 0.f); vl.y = fmaxf(vl.y, 0.f);
                vh.x = fmaxf(vh.x, 0.f); vh.y = fmaxf(vh.y, 0.f);
            }
            if (HALF_OUT) {
                __half* oh = (__half*)outp + (size_t)b * o_bstride;
                __half2 h0 = __floats2half2_rn(vl.x, vl.y);
                __half2 h1 = __floats2half2_rn(vh.x, vh.y);
                *(__half2*)(oh + (size_t)ml * HW + nn) = h0;
                *(__half2*)(oh + (size_t)mh * HW + nn) = h1;
            } else {
                float* of = (float*)outp + (size_t)b * o_bstride;
                if (RESID) {
                    const float* rp = resid + (size_t)b * o_bstride;
                    float2 rl = *(const float2*)(rp + (size_t)ml * HW + nn);
                    float2 rh = *(const float2*)(rp + (size_t)mh * HW + nn);
                    vl.x += rl.x; vl.y += rl.y; vh.x += rh.x; vh.y += rh.y;
                }
                *(float2*)(of + (size_t)ml * HW + nn) = vl;
                *(float2*)(of + (size_t)mh * HW + nn) = vh;
            }
        }
    }
}

// ---------------------------------------------------------------------------
// attn_out: y[b][c][n] = sum_s Vp[b][c][s] * P[b][s][n]   (fp16 mma, K=112
// entirely in smem, single shot). CTA 128c x 128n, 8 warps.
// ---------------------------------------------------------------------------
#define AO_ASTR 120
#define AO_SMEM (128*AO_ASTR*2 + 112*B_STRH*2)   // 30720 + 30464 = 61184

__global__ __launch_bounds__(256) void attn_out_kernel(
    const __half* __restrict__ Vp, const __half* __restrict__ P, __half* __restrict__ y)
{
    extern __shared__ __align__(16) char smc[];
    const uint32_t sb = smem_u32(smc);
    const uint32_t sA = sb, sB = sb + 128*AO_ASTR*2;
    const int tid = threadIdx.x, lane = tid & 31, wid = tid >> 5;
    const int gidr = lane >> 2, t4 = lane & 3;
    const int wm = wid >> 2, wn = wid & 3;
    const int n0 = blockIdx.x * 128, c0 = blockIdx.y * 128, b = blockIdx.z;

    const __half* gA = Vp + (size_t)b * CV * 112 + (size_t)c0 * 112;
    const __half* gB = P + (size_t)b * 112 * HW + n0;

    #pragma unroll
    for (int it = 0; it < 7; ++it) {           // A: 128 rows x 14 chunks
        int idx = it * 256 + tid;
        int r = idx / 14, c = idx - r * 14;
        cpa16(sA + (uint32_t)(r * AO_ASTR + c * 8) * 2, gA + (size_t)r * 112 + c * 8);
    }
    #pragma unroll
    for (int it = 0; it < 7; ++it) {           // B: 112 rows x 16 chunks
        int idx = it * 256 + tid;
        int r = idx >> 4, c = idx & 15;
        cpa16(sB + (uint32_t)(r * B_STRH + c * 8) * 2, gB + (size_t)r * HW + c * 8);
    }
    asm volatile("cp.async.commit_group;\ncp.async.wait_group 0;" ::: "memory");
    __syncthreads();

    const int a_row = lane & 15, a_koff = (lane >> 4) * 8;
    const int b_krow = ((lane >> 3) & 1) * 8 + (lane & 7);
    const int b_noff = (lane >> 4) * 8;

    float acc[4][4][4];
    #pragma unroll
    for (int mt = 0; mt < 4; ++mt)
        #pragma unroll
        for (int nt = 0; nt < 4; ++nt)
            #pragma unroll
            for (int r = 0; r < 4; ++r) acc[mt][nt][r] = 0.f;

    #pragma unroll
    for (int s16 = 0; s16 < 7; ++s16) {
        const int kk = s16 * 16;
        uint32_t af[4][4], bf[4][2];
        #pragma unroll
        for (int mt = 0; mt < 4; ++mt) {
            int row = wm * 64 + mt * 16 + a_row;
            ldsm_x4(af[mt], sA + (uint32_t)(row * AO_ASTR + kk + a_koff) * 2);
        }
        #pragma unroll
        for (int nt2 = 0; nt2 < 2; ++nt2) {
            uint32_t r4[4];
            int ncol = wn * 32 + nt2 * 16 + b_noff;
            ldsm_x4_t(r4, sB + (uint32_t)((kk + b_krow) * B_STRH + ncol) * 2);
            bf[nt2*2][0] = r4[0]; bf[nt2*2][1] = r4[1];
            bf[nt2*2+1][0] = r4[2]; bf[nt2*2+1][1] = r4[3];
        }
        #pragma unroll
        for (int mt = 0; mt < 4; ++mt)
            #pragma unroll
            for (int nt = 0; nt < 4; ++nt)
                mma_f16(acc[mt][nt], af[mt], bf[nt]);
    }

    __half* yb = y + (size_t)b * CV * HW;
    #pragma unroll
    for (int mt = 0; mt < 4; ++mt) {
        const int ml = c0 + wm * 64 + mt * 16 + gidr;
        #pragma unroll
        for (int nt = 0; nt < 4; ++nt) {
            const int nn = n0 + wn * 32 + nt * 8 + 2 * t4;
            *(__half2*)(yb + (size_t)ml * HW + nn) =
                __floats2half2_rn(acc[mt][nt][0], acc[mt][nt][1]);
            *(__half2*)(yb + (size_t)(ml + 8) * HW + nn) =
                __floats2half2_rn(acc[mt][nt][2], acc[mt][nt][3]);
        }
    }
}

// ---------------------------------------------------------------------------
// fp32 -> fp16 conversion
// ---------------------------------------------------------------------------
__global__ __launch_bounds__(256) void cvt_half_kernel(
    const float* __restrict__ a, __half* __restrict__ o, int n)
{
    int i = blockIdx.x * 256 + threadIdx.x;
    if (i < n) o[i] = __float2half_rn(a[i]);
}
__global__ __launch_bounds__(256) void cvt_half_v8_kernel(
    const float4* __restrict__ a, uint4* __restrict__ o, int n8)
{
    int i = blockIdx.x * 256 + threadIdx.x;
    if (i < n8) {
        float4 f0 = a[2*i], f1 = a[2*i+1];
        __half2 h0 = __floats2half2_rn(f0.x, f0.y);
        __half2 h1 = __floats2half2_rn(f0.z, f0.w);
        __half2 h2 = __floats2half2_rn(f1.x, f1.y);
        __half2 h3 = __floats2half2_rn(f1.z, f1.w);
        uint4 u;
        u.x = *(uint32_t*)&h0; u.y = *(uint32_t*)&h1;
        u.z = *(uint32_t*)&h2; u.w = *(uint32_t*)&h3;
        o[i] = u;
    }
}

// ---------------------------------------------------------------------------
// PSP adaptive max pool, half in / half out.
// mode 0: out[(b*C + c)*112 + cell]   (value: [c][s] pad 112)
// mode 1: out[(b*128 + cell)*C + c]   (key:   [s pad128][c])
// ---------------------------------------------------------------------------
__global__ __launch_bounds__(128) void psp_kernel(
    const __half* __restrict__ in, __half* __restrict__ out, int C, int mode)
{
    __shared__ __align__(16) float sp[4096];
    __shared__ float rm[17][64];
    __shared__ float s8v[64];
    const int bc = blockIdx.x;
    const int b = bc / C, c = bc - b * C;
    const int tid = threadIdx.x;
    const __half* plane = in + (size_t)bc * 4096;
    for (int i = tid; i < 512; i += 128) {
        uint4 u = ((const uint4*)plane)[i];
        __half2* h = (__half2*)&u;
        float2 f0 = __half22float2(h[0]), f1 = __half22float2(h[1]);
        float2 f2 = __half22float2(h[2]), f3 = __half22float2(h[3]);
        float* d = sp + i * 8;
        d[0]=f0.x; d[1]=f0.y; d[2]=f1.x; d[3]=f1.y;
        d[4]=f2.x; d[5]=f2.y; d[6]=f3.x; d[7]=f3.y;
    }
    __syncthreads();

    const int cs[17] = {0,21,42, 0,10,21,32,42,53, 0,8,16,24,32,40,48,56};
    const int ce[17] = {22,43,64, 11,22,32,43,54,64, 8,16,24,32,40,48,56,64};
    for (int idx = tid; idx < 17 * 64; idx += 128) {
        int seg = idx >> 6, row = idx & 63;
        const float* rp = sp + row * 64;
        float m = -3.402823e38f;
        for (int cc = cs[seg]; cc < ce[seg]; ++cc) m = fmaxf(m, rp[cc]);
        rm[seg][row] = m;
    }
    __syncthreads();

    float m = -3.402823e38f;
    int cell = -1;
    if (tid < 64) {                        // s=8
        int i = tid >> 3, j = tid & 7;
        for (int r = i * 8; r < i * 8 + 8; ++r) m = fmaxf(m, rm[9 + j][r]);
        s8v[tid] = m; cell = 46 + tid;
    } else if (tid < 100) {                // s=6
        const int st[6] = {0,10,21,32,42,53}, en[6] = {11,22,32,43,54,64};
        int t = tid - 64, i = t / 6, j = t - i * 6;
        for (int r = st[i]; r < en[i]; ++r) m = fmaxf(m, rm[3 + j][r]);
        cell = 10 + t;
    } else if (tid < 109) {                // s=3
        const int st[3] = {0,21,42}, en[3] = {22,43,64};
        int t = tid - 100, i = t / 3, j = t - i * 3;
        for (int r = st[i]; r < en[i]; ++r) m = fmaxf(m, rm[j][r]);
        cell = 1 + t;
    }
    if (cell >= 0) {
        size_t o = mode ? ((size_t)(b * 128 + cell) * C + c)
                        : ((size_t)bc * 112 + cell);
        out[o] = __float2half_rn(m);
    }
    __syncthreads();
    if (tid == 0) {
        float mm = s8v[0];
        for (int i = 1; i < 64; ++i) mm = fmaxf(mm, s8v[i]);
        size_t o = mode ? ((size_t)(b * 128) * C + c) : ((size_t)bc * 112);
        out[o] = __float2half_rn(mm);
    }
}

// ---------------------------------------------------------------------------
// Column softmax over s (110) for each n: p[s][n] = softmax_s(scores[s][n]).
// Block: 128 threads = 128 n-columns; scores tile staged in smem.
// ---------------------------------------------------------------------------
__global__ __launch_bounds__(128) void softmax_kernel(
    const __half* __restrict__ s_h, __half* __restrict__ p_h)
{
    __shared__ __align__(16) __half ss[SS * 128];
    const int b = blockIdx.y, n0 = blockIdx.x * 128;
    const int tid = threadIdx.x;
    const __half* sbx = s_h + (size_t)b * 128 * HW + n0;
    for (int i = tid; i < SS * 16; i += 128) {
        int row = i >> 4, col = (i & 15) * 8;
        *(uint4*)&ss[row * 128 + col] = *(const uint4*)&sbx[(size_t)row * HW + col];
    }
    __syncthreads();

    float mx = -3.402823e38f;
    #pragma unroll 2
    for (int s = 0; s < SS; ++s) mx = fmaxf(mx, __half2float(ss[s * 128 + tid]));
    float sum = 0.f;
    #pragma unroll 2
    for (int s = 0; s < SS; ++s) sum += __expf(__half2float(ss[s * 128 + tid]) - mx);
    const float inv = 1.f / sum;
    __half* pb = p_h + (size_t)b * 112 * HW + n0 + tid;
    #pragma unroll 2
    for (int s = 0; s < SS; ++s)
        pb[(size_t)s * HW] = __float2half_rn(__expf(__half2float(ss[s * 128 + tid]) - mx) * inv);
}

// ---------------------------------------------------------------------------
extern "C" void kernel_launch(void* const* d_in, const int* in_sizes, int n_in,
                              void* d_out, int out_size)
{
    const float* x        = (const float*)d_in[0];
    const float* qk_w     = (const float*)d_in[1];
    const float* qk_gamma = (const float*)d_in[2];
    const float* qk_beta  = (const float*)d_in[3];
    const float* qk_mean  = (const float*)d_in[4];
    const float* qk_var   = (const float*)d_in[5];
    const float* v_w      = (const float*)d_in[6];
    const float* v_gamma  = (const float*)d_in[7];
    const float* v_beta   = (const float*)d_in[8];
    const float* v_mean   = (const float*)d_in[9];
    const float* v_var    = (const float*)d_in[10];
    const float* out_w    = (const float*)d_in[11];
    const float* o_gamma  = (const float*)d_in[12];
    const float* o_beta   = (const float*)d_in[13];
    const float* o_mean   = (const float*)d_in[14];
    const float* o_var    = (const float*)d_in[15];
    float* out = (float*)d_out;

    __half *xh, *qkh, *valh, *keyh, *vpsp, *sh, *ph, *yh, *wq, *wv, *wo;
    cudaGetSymbolAddress((void**)&xh,   g_xh);
    cudaGetSymbolAddress((void**)&qkh,  g_qkh);
    cudaGetSymbolAddress((void**)&valh, g_valh);
    cudaGetSymbolAddress((void**)&keyh, g_keyh);
    cudaGetSymbolAddress((void**)&vpsp, g_vpsp);
    cudaGetSymbolAddress((void**)&sh,   g_sh);
    cudaGetSymbolAddress((void**)&ph,   g_ph);
    cudaGetSymbolAddress((void**)&yh,   g_yh);
    cudaGetSymbolAddress((void**)&wq,   g_wq);
    cudaGetSymbolAddress((void**)&wv,   g_wv);
    cudaGetSymbolAddress((void**)&wo,   g_wo);

    cudaFuncSetAttribute(gemm_kernel<true, true, false, true>,
                         cudaFuncAttributeMaxDynamicSharedMemorySize, GEMM_SMEM);
    cudaFuncSetAttribute(gemm_kernel<false, false, false, true>,
                         cudaFuncAttributeMaxDynamicSharedMemorySize, GEMM_SMEM);
    cudaFuncSetAttribute(gemm_kernel<true, false, true, false>,
                         cudaFuncAttributeMaxDynamicSharedMemorySize, GEMM_SMEM);
    cudaFuncSetAttribute(attn_out_kernel,
                         cudaFuncAttributeMaxDynamicSharedMemorySize, AO_SMEM);

    // 0) fp16 conversions
    cvt_half_kernel<<<(CK*CIN + 255) / 256, 256>>>(qk_w, wq, CK*CIN);
    cvt_half_kernel<<<(CV*CIN + 255) / 256, 256>>>(v_w,  wv, CV*CIN);
    cvt_half_kernel<<<(CIN*CV + 255) / 256, 256>>>(out_w, wo, CIN*CV);
    cvt_half_v8_kernel<<<(BB*CIN*HW/8 + 255) / 256, 256>>>(
        (const float4*)x, (uint4*)xh, BB*CIN*HW/8);

    // 1) qk = relu(bn(conv(x, wq)))  -> half [b][c][n]
    gemm_kernel<true, true, false, true><<<dim3(32, 2, BB), 256, GEMM_SMEM>>>(
        wq, 0, xh, (size_t)CIN*HW, qk_gamma, qk_beta, qk_mean, qk_var,
        1.f, nullptr, qkh, (size_t)CK*HW, CIN);
    // 2) val = relu(bn(conv(x, wv))) -> half
    gemm_kernel<true, true, false, true><<<dim3(32, 4, BB), 256, GEMM_SMEM>>>(
        wv, 0, xh, (size_t)CIN*HW, v_gamma, v_beta, v_mean, v_var,
        1.f, nullptr, valh, (size_t)CV*HW, CIN);
    // 3) key = psp(qk) [s][c]; value = psp(val) [c][s]
    psp_kernel<<<BB * CK, 128>>>(qkh,  keyh, CK, 1);
    psp_kernel<<<BB * CV, 128>>>(valh, vpsp, CV, 0);
    // 4) raw scores [s][n] = (key @ qk) / 16  via GEMM
    gemm_kernel<false, false, false, true><<<dim3(32, 1, BB), 256, GEMM_SMEM>>>(
        keyh, (size_t)128*CK, qkh, (size_t)CK*HW, nullptr, nullptr, nullptr, nullptr,
        0.0625f, nullptr, sh, (size_t)128*HW, CK);
    // 5) column softmax -> p [s][n] half
    softmax_kernel<<<dim3(32, BB), 128>>>(sh, ph);
    // 6) y[c][n] = value[c][s] @ p[s][n]
    attn_out_kernel<<<dim3(32, 4, BB), 256, AO_SMEM>>>(vpsp, ph, yh);
    // 7) out = x + bn(conv(y, wo))
    gemm_kernel<true, false, true, false><<<dim3(32, 4, BB), 256, GEMM_SMEM>>>(
        wo, 0, yh, (size_t)CV*HW, o_gamma, o_beta, o_mean, o_var,
        1.f, x, out, (size_t)CIN*HW, CV);
}

// round 6
// speedup vs baseline: 2.6814x; 1.0076x over previous
#include <cuda_runtime.h>
#include <cuda_fp16.h>
#include <cstdint>
#include <math.h>

#define BB   8
#define CIN  512
#define CK   256
#define CV   512
#define HW   4096
#define SS   110

// Scratch (__device__ globals are zero-initialized; pad regions never written
// stay zero -> free zero-padding).
__device__ __align__(16) __half g_xh    [BB*CIN*HW];    // [b][k][n]
__device__ __align__(16) __half g_qkh   [BB*CK*HW];     // [b][c][n]
__device__ __align__(16) __half g_valh  [BB*CV*HW];     // [b][c][n]
__device__ __align__(16) __half g_keyh  [BB*128*CK];    // [b][s(pad128)][c]
__device__ __align__(16) __half g_vpsp  [BB*CV*112];    // [b][c][s(pad112)]
__device__ __align__(16) __half g_sh    [BB*128*HW];    // [b][s(pad128)][n]
__device__ __align__(16) __half g_ph    [BB*112*HW];    // [b][s(pad112)][n]
__device__ __align__(16) __half g_yh    [BB*CV*HW];     // [b][c][n]
__device__ __align__(16) __half g_wq    [CK*CIN];
__device__ __align__(16) __half g_wv    [CV*CIN];
__device__ __align__(16) __half g_wo    [CIN*CV];

// ---------------------------------------------------------------------------
__device__ __forceinline__ uint32_t smem_u32(const void* p) {
    uint32_t a;
    asm("{ .reg .u64 t; cvta.to.shared.u64 t, %1; cvt.u32.u64 %0, t; }" : "=r"(a) : "l"(p));
    return a;
}
__device__ __forceinline__ void ldsm_x4(uint32_t* r, uint32_t addr) {
    asm volatile("ldmatrix.sync.aligned.m8n8.x4.shared.b16 {%0,%1,%2,%3}, [%4];"
        : "=r"(r[0]), "=r"(r[1]), "=r"(r[2]), "=r"(r[3]) : "r"(addr));
}
__device__ __forceinline__ void ldsm_x4_t(uint32_t* r, uint32_t addr) {
    asm volatile("ldmatrix.sync.aligned.m8n8.x4.trans.shared.b16 {%0,%1,%2,%3}, [%4];"
        : "=r"(r[0]), "=r"(r[1]), "=r"(r[2]), "=r"(r[3]) : "r"(addr));
}
__device__ __forceinline__ void mma_f16(float* c, const uint32_t* a, const uint32_t* b) {
    asm volatile(
        "mma.sync.aligned.m16n8k16.row.col.f32.f16.f16.f32 "
        "{%0,%1,%2,%3}, {%4,%5,%6,%7}, {%8,%9}, {%0,%1,%2,%3};"
        : "+f"(c[0]), "+f"(c[1]), "+f"(c[2]), "+f"(c[3])
        : "r"(a[0]), "r"(a[1]), "r"(a[2]), "r"(a[3]), "r"(b[0]), "r"(b[1]));
}
__device__ __forceinline__ void cpa16(uint32_t dst, const void* src) {
    asm volatile("cp.async.cg.shared.global [%0], [%1], 16;" :: "r"(dst), "l"(src));
}

// ---------------------------------------------------------------------------
// Generalized GEMM: out[b,m,n] = epi( sum_k A[m,k] * B[b,k,n] )
// CTA 128m x 128n, 8 warps (2x4), warp 64x32. K staged 32, 4-stage pipeline.
// FUSED: blockIdx.y<2 -> branch 1 (A,params,out), else branch 2.
// ---------------------------------------------------------------------------
#define A_STRH 40
#define B_STRH 136
#define A_STG  (128*A_STRH*2)              // 10240 B
#define B_STG  (32*B_STRH*2)               // 8704 B
#define STG    (A_STG + B_STG)             // 18944 B
#define NSTAGE 4
#define GEMM_SMEM (NSTAGE*STG)             // 75776 B

template<bool FUSED, bool BN, bool RELU, bool RESID, bool HALF_OUT>
__global__ __launch_bounds__(256, 2) void gemm_kernel(
    const __half* __restrict__ A, size_t a_bstride,
    const __half* __restrict__ Bm, size_t b_bstride,
    const float* __restrict__ gamma, const float* __restrict__ beta,
    const float* __restrict__ mean,  const float* __restrict__ var,
    float uscale,
    const float* __restrict__ resid,
    void* __restrict__ outp, size_t o_bstride,
    int Ktot,
    // FUSED branch-2 args
    const __half* __restrict__ A2,
    const float* __restrict__ gamma2, const float* __restrict__ beta2,
    const float* __restrict__ mean2,  const float* __restrict__ var2,
    void* __restrict__ outp2, size_t o_bstride2)
{
    extern __shared__ __align__(16) char smc[];
    const uint32_t sb = smem_u32(smc);
    const int tid = threadIdx.x, lane = tid & 31, wid = tid >> 5;
    const int gidr = lane >> 2, t4 = lane & 3;
    const int wm = wid >> 2, wn = wid & 3;
    const int n0 = blockIdx.x * 128, b = blockIdx.z;
    const int NK = Ktot >> 5;

    int m0 = blockIdx.y * 128;
    const __half* Ause = A;
    const float *g_ = gamma, *be_ = beta, *me_ = mean, *va_ = var;
    void* ouse = outp;
    size_t ostr = o_bstride;
    if (FUSED && blockIdx.y >= 2) {
        m0 = (blockIdx.y - 2) * 128;
        Ause = A2; g_ = gamma2; be_ = beta2; me_ = mean2; va_ = var2;
        ouse = outp2; ostr = o_bstride2;
    }

    const __half* gA = Ause + (size_t)b * a_bstride + (size_t)m0 * Ktot;
    const __half* gB = Bm + (size_t)b * b_bstride + n0;

    auto load_stage = [&](int s) {
        const uint32_t base = sb + (uint32_t)(s & (NSTAGE-1)) * STG;
        #pragma unroll
        for (int it = 0; it < 2; ++it) {            // A: 128r x 4 chunks
            int idx = it * 256 + tid;
            int r = idx >> 2, c = idx & 3;
            cpa16(base + (uint32_t)(r * A_STRH + c * 8) * 2,
                  gA + (size_t)r * Ktot + s * 32 + c * 8);
        }
        #pragma unroll
        for (int it = 0; it < 2; ++it) {            // B: 32r x 16 chunks
            int idx = it * 256 + tid;
            int r = idx >> 4, c = idx & 15;
            cpa16(base + A_STG + (uint32_t)(r * B_STRH + c * 8) * 2,
                  gB + (size_t)(s * 32 + r) * HW + c * 8);
        }
        asm volatile("cp.async.commit_group;" ::: "memory");
    };

    float acc[4][4][4];
    #pragma unroll
    for (int mt = 0; mt < 4; ++mt)
        #pragma unroll
        for (int nt = 0; nt < 4; ++nt)
            #pragma unroll
            for (int r = 0; r < 4; ++r) acc[mt][nt][r] = 0.f;

    for (int s = 0; s < NSTAGE - 1 && s < NK; ++s) load_stage(s);
    asm volatile("cp.async.wait_group 2;" ::: "memory");
    __syncthreads();

    const int a_row = lane & 15, a_koff = (lane >> 4) * 8;
    const int b_krow = ((lane >> 3) & 1) * 8 + (lane & 7);
    const int b_noff = (lane >> 4) * 8;

    for (int kt = 0; kt < NK; ++kt) {
        if (kt + NSTAGE - 1 < NK) load_stage(kt + NSTAGE - 1);
        else asm volatile("cp.async.commit_group;" ::: "memory");

        const uint32_t sA = sb + (uint32_t)(kt & (NSTAGE-1)) * STG;
        const uint32_t sB = sA + A_STG;
        #pragma unroll
        for (int s16 = 0; s16 < 2; ++s16) {
            const int kk = s16 * 16;
            uint32_t af[4][4], bf[4][2];
            #pragma unroll
            for (int mt = 0; mt < 4; ++mt) {
                int row = wm * 64 + mt * 16 + a_row;
                ldsm_x4(af[mt], sA + (uint32_t)(row * A_STRH + kk + a_koff) * 2);
            }
            #pragma unroll
            for (int nt2 = 0; nt2 < 2; ++nt2) {
                uint32_t r4[4];
                int ncol = wn * 32 + nt2 * 16 + b_noff;
                ldsm_x4_t(r4, sB + (uint32_t)((kk + b_krow) * B_STRH + ncol) * 2);
                bf[nt2*2][0] = r4[0]; bf[nt2*2][1] = r4[1];
                bf[nt2*2+1][0] = r4[2]; bf[nt2*2+1][1] = r4[3];
            }
            #pragma unroll
            for (int mt = 0; mt < 4; ++mt)
                #pragma unroll
                for (int nt = 0; nt < 4; ++nt)
                    mma_f16(acc[mt][nt], af[mt], bf[nt]);
        }
        asm volatile("cp.async.wait_group 2;" ::: "memory");
        __syncthreads();
    }

    // Epilogue
    #pragma unroll
    for (int mt = 0; mt < 4; ++mt) {
        const int ml = m0 + wm * 64 + mt * 16 + gidr;
        const int mh = ml + 8;
        float scl, ttl, sch, tth;
        if (BN) {
            scl = g_[ml] * rsqrtf(va_[ml] + 1e-5f);
            ttl = be_[ml] - me_[ml] * scl;
            sch = g_[mh] * rsqrtf(va_[mh] + 1e-5f);
            tth = be_[mh] - me_[mh] * sch;
        } else { scl = uscale; ttl = 0.f; sch = uscale; tth = 0.f; }
        #pragma unroll
        for (int nt = 0; nt < 4; ++nt) {
            const int nn = n0 + wn * 32 + nt * 8 + 2 * t4;
            float2 vl, vh;
            vl.x = acc[mt][nt][0] * scl + ttl;
            vl.y = acc[mt][nt][1] * scl + ttl;
            vh.x = acc[mt][nt][2] * sch + tth;
            vh.y = acc[mt][nt][3] * sch + tth;
            if (RELU) {
                vl.x = fmaxf(vl.x, 0.f); vl.y = fmaxf(vl.y, 0.f);
                vh.x = fmaxf(vh.x, 0.f); vh.y = fmaxf(vh.y, 0.f);
            }
            if (HALF_OUT) {
                __half* oh = (__half*)ouse + (size_t)b * ostr;
                *(__half2*)(oh + (size_t)ml * HW + nn) = __floats2half2_rn(vl.x, vl.y);
                *(__half2*)(oh + (size_t)mh * HW + nn) = __floats2half2_rn(vh.x, vh.y);
            } else {
                float* of = (float*)ouse + (size_t)b * ostr;
                if (RESID) {
                    const float* rp = resid + (size_t)b * ostr;
                    float2 rl = *(const float2*)(rp + (size_t)ml * HW + nn);
                    float2 rh = *(const float2*)(rp + (size_t)mh * HW + nn);
                    vl.x += rl.x; vl.y += rl.y; vh.x += rh.x; vh.y += rh.y;
                }
                *(float2*)(of + (size_t)ml * HW + nn) = vl;
                *(float2*)(of + (size_t)mh * HW + nn) = vh;
            }
        }
    }
}

// ---------------------------------------------------------------------------
// attn_out: y[b][c][n] = sum_s Vp[b][c][s] * P[b][s][n]  (K=112 single shot)
// ---------------------------------------------------------------------------
#define AO_ASTR 120
#define AO_SMEM (128*AO_ASTR*2 + 112*B_STRH*2)   // 61184

__global__ __launch_bounds__(256, 2) void attn_out_kernel(
    const __half* __restrict__ Vp, const __half* __restrict__ P, __half* __restrict__ y)
{
    extern __shared__ __align__(16) char smc[];
    const uint32_t sb = smem_u32(smc);
    const uint32_t sA = sb, sB = sb + 128*AO_ASTR*2;
    const int tid = threadIdx.x, lane = tid & 31, wid = tid >> 5;
    const int gidr = lane >> 2, t4 = lane & 3;
    const int wm = wid >> 2, wn = wid & 3;
    const int n0 = blockIdx.x * 128, c0 = blockIdx.y * 128, b = blockIdx.z;

    const __half* gA = Vp + (size_t)b * CV * 112 + (size_t)c0 * 112;
    const __half* gB = P + (size_t)b * 112 * HW + n0;

    #pragma unroll
    for (int it = 0; it < 7; ++it) {
        int idx = it * 256 + tid;
        int r = idx / 14, c = idx - r * 14;
        cpa16(sA + (uint32_t)(r * AO_ASTR + c * 8) * 2, gA + (size_t)r * 112 + c * 8);
    }
    #pragma unroll
    for (int it = 0; it < 7; ++it) {
        int idx = it * 256 + tid;
        int r = idx >> 4, c = idx & 15;
        cpa16(sB + (uint32_t)(r * B_STRH + c * 8) * 2, gB + (size_t)r * HW + c * 8);
    }
    asm volatile("cp.async.commit_group;\ncp.async.wait_group 0;" ::: "memory");
    __syncthreads();

    const int a_row = lane & 15, a_koff = (lane >> 4) * 8;
    const int b_krow = ((lane >> 3) & 1) * 8 + (lane & 7);
    const int b_noff = (lane >> 4) * 8;

    float acc[4][4][4];
    #pragma unroll
    for (int mt = 0; mt < 4; ++mt)
        #pragma unroll
        for (int nt = 0; nt < 4; ++nt)
            #pragma unroll
            for (int r = 0; r < 4; ++r) acc[mt][nt][r] = 0.f;

    #pragma unroll
    for (int s16 = 0; s16 < 7; ++s16) {
        const int kk = s16 * 16;
        uint32_t af[4][4], bf[4][2];
        #pragma unroll
        for (int mt = 0; mt < 4; ++mt) {
            int row = wm * 64 + mt * 16 + a_row;
            ldsm_x4(af[mt], sA + (uint32_t)(row * AO_ASTR + kk + a_koff) * 2);
        }
        #pragma unroll
        for (int nt2 = 0; nt2 < 2; ++nt2) {
            uint32_t r4[4];
            int ncol = wn * 32 + nt2 * 16 + b_noff;
            ldsm_x4_t(r4, sB + (uint32_t)((kk + b_krow) * B_STRH + ncol) * 2);
            bf[nt2*2][0] = r4[0]; bf[nt2*2][1] = r4[1];
            bf[nt2*2+1][0] = r4[2]; bf[nt2*2+1][1] = r4[3];
        }
        #pragma unroll
        for (int mt = 0; mt < 4; ++mt)
            #pragma unroll
            for (int nt = 0; nt < 4; ++nt)
                mma_f16(acc[mt][nt], af[mt], bf[nt]);
    }

    __half* yb = y + (size_t)b * CV * HW;
    #pragma unroll
    for (int mt = 0; mt < 4; ++mt) {
        const int ml = c0 + wm * 64 + mt * 16 + gidr;
        #pragma unroll
        for (int nt = 0; nt < 4; ++nt) {
            const int nn = n0 + wn * 32 + nt * 8 + 2 * t4;
            *(__half2*)(yb + (size_t)ml * HW + nn) =
                __floats2half2_rn(acc[mt][nt][0], acc[mt][nt][1]);
            *(__half2*)(yb + (size_t)(ml + 8) * HW + nn) =
                __floats2half2_rn(acc[mt][nt][2], acc[mt][nt][3]);
        }
    }
}

// ---------------------------------------------------------------------------
// All three weight conversions in one launch
// ---------------------------------------------------------------------------
__global__ __launch_bounds__(256) void cvt_weights_kernel(
    const float* __restrict__ wq, const float* __restrict__ wv,
    const float* __restrict__ wo,
    __half* __restrict__ oq, __half* __restrict__ ov, __half* __restrict__ oo)
{
    int i = blockIdx.x * 256 + threadIdx.x;
    if (i < CK*CIN) oq[i] = __float2half_rn(wq[i]);
    if (i < CV*CIN) { ov[i] = __float2half_rn(wv[i]); oo[i] = __float2half_rn(wo[i]); }
}
__global__ __launch_bounds__(256) void cvt_half_v8_kernel(
    const float4* __restrict__ a, uint4* __restrict__ o, int n8)
{
    int i = blockIdx.x * 256 + threadIdx.x;
    if (i < n8) {
        float4 f0 = a[2*i], f1 = a[2*i+1];
        __half2 h0 = __floats2half2_rn(f0.x, f0.y);
        __half2 h1 = __floats2half2_rn(f0.z, f0.w);
        __half2 h2 = __floats2half2_rn(f1.x, f1.y);
        __half2 h3 = __floats2half2_rn(f1.z, f1.w);
        uint4 u;
        u.x = *(uint32_t*)&h0; u.y = *(uint32_t*)&h1;
        u.z = *(uint32_t*)&h2; u.w = *(uint32_t*)&h3;
        o[i] = u;
    }
}

// ---------------------------------------------------------------------------
// PSP adaptive max pool, half in / half out.
// mode 0: out[(b*C + c)*112 + cell]   (value: [c][s] pad 112)
// mode 1: out[(b*128 + cell)*C + c]   (key:   [s pad128][c])
// ---------------------------------------------------------------------------
__global__ __launch_bounds__(128) void psp_kernel(
    const __half* __restrict__ in, __half* __restrict__ out, int C, int mode)
{
    __shared__ __align__(16) float sp[4096];
    __shared__ float rm[17][64];
    __shared__ float s8v[64];
    const int bc = blockIdx.x;
    const int b = bc / C, c = bc - b * C;
    const int tid = threadIdx.x;
    const __half* plane = in + (size_t)bc * 4096;
    for (int i = tid; i < 512; i += 128) {
        uint4 u = ((const uint4*)plane)[i];
        __half2* h = (__half2*)&u;
        float2 f0 = __half22float2(h[0]), f1 = __half22float2(h[1]);
        float2 f2 = __half22float2(h[2]), f3 = __half22float2(h[3]);
        float* d = sp + i * 8;
        d[0]=f0.x; d[1]=f0.y; d[2]=f1.x; d[3]=f1.y;
        d[4]=f2.x; d[5]=f2.y; d[6]=f3.x; d[7]=f3.y;
    }
    __syncthreads();

    const int cs[17] = {0,21,42, 0,10,21,32,42,53, 0,8,16,24,32,40,48,56};
    const int ce[17] = {22,43,64, 11,22,32,43,54,64, 8,16,24,32,40,48,56,64};
    for (int idx = tid; idx < 17 * 64; idx += 128) {
        int seg = idx >> 6, row = idx & 63;
        const float* rp = sp + row * 64;
        float m = -3.402823e38f;
        for (int cc = cs[seg]; cc < ce[seg]; ++cc) m = fmaxf(m, rp[cc]);
        rm[seg][row] = m;
    }
    __syncthreads();

    float m = -3.402823e38f;
    int cell = -1;
    if (tid < 64) {                        // s=8
        int i = tid >> 3, j = tid & 7;
        for (int r = i * 8; r < i * 8 + 8; ++r) m = fmaxf(m, rm[9 + j][r]);
        s8v[tid] = m; cell = 46 + tid;
    } else if (tid < 100) {                // s=6
        const int st[6] = {0,10,21,32,42,53}, en[6] = {11,22,32,43,54,64};
        int t = tid - 64, i = t / 6, j = t - i * 6;
        for (int r = st[i]; r < en[i]; ++r) m = fmaxf(m, rm[3 + j][r]);
        cell = 10 + t;
    } else if (tid < 109) {                // s=3
        const int st[3] = {0,21,42}, en[3] = {22,43,64};
        int t = tid - 100, i = t / 3, j = t - i * 3;
        for (int r = st[i]; r < en[i]; ++r) m = fmaxf(m, rm[j][r]);
        cell = 1 + t;
    }
    if (cell >= 0) {
        size_t o = mode ? ((size_t)(b * 128 + cell) * C + c)
                        : ((size_t)bc * 112 + cell);
        out[o] = __float2half_rn(m);
    }
    __syncthreads();
    if (tid == 0) {
        float mm = s8v[0];
        for (int i = 1; i < 64; ++i) mm = fmaxf(mm, s8v[i]);
        size_t o = mode ? ((size_t)(b * 128) * C + c) : ((size_t)bc * 112);
        out[o] = __float2half_rn(mm);
    }
}

// ---------------------------------------------------------------------------
// Column softmax over s (110) for each n.
// ---------------------------------------------------------------------------
__global__ __launch_bounds__(128) void softmax_kernel(
    const __half* __restrict__ s_h, __half* __restrict__ p_h)
{
    __shared__ __align__(16) __half ss[SS * 128];
    const int b = blockIdx.y, n0 = blockIdx.x * 128;
    const int tid = threadIdx.x;
    const __half* sbx = s_h + (size_t)b * 128 * HW + n0;
    for (int i = tid; i < SS * 16; i += 128) {
        int row = i >> 4, col = (i & 15) * 8;
        *(uint4*)&ss[row * 128 + col] = *(const uint4*)&sbx[(size_t)row * HW + col];
    }
    __syncthreads();

    float mx = -3.402823e38f;
    #pragma unroll 2
    for (int s = 0; s < SS; ++s) mx = fmaxf(mx, __half2float(ss[s * 128 + tid]));
    float sum = 0.f;
    #pragma unroll 2
    for (int s = 0; s < SS; ++s) sum += __expf(__half2float(ss[s * 128 + tid]) - mx);
    const float inv = 1.f / sum;
    __half* pb = p_h + (size_t)b * 112 * HW + n0 + tid;
    #pragma unroll 2
    for (int s = 0; s < SS; ++s)
        pb[(size_t)s * HW] = __float2half_rn(__expf(__half2float(ss[s * 128 + tid]) - mx) * inv);
}

// ---------------------------------------------------------------------------
extern "C" void kernel_launch(void* const* d_in, const int* in_sizes, int n_in,
                              void* d_out, int out_size)
{
    const float* x        = (const float*)d_in[0];
    const float* qk_w     = (const float*)d_in[1];
    const float* qk_gamma = (const float*)d_in[2];
    const float* qk_beta  = (const float*)d_in[3];
    const float* qk_mean  = (const float*)d_in[4];
    const float* qk_var   = (const float*)d_in[5];
    const float* v_w      = (const float*)d_in[6];
    const float* v_gamma  = (const float*)d_in[7];
    const float* v_beta   = (const float*)d_in[8];
    const float* v_mean   = (const float*)d_in[9];
    const float* v_var    = (const float*)d_in[10];
    const float* out_w    = (const float*)d_in[11];
    const float* o_gamma  = (const float*)d_in[12];
    const float* o_beta   = (const float*)d_in[13];
    const float* o_mean   = (const float*)d_in[14];
    const float* o_var    = (const float*)d_in[15];
    float* out = (float*)d_out;

    __half *xh, *qkh, *valh, *keyh, *vpsp, *sh, *ph, *yh, *wq, *wv, *wo;
    cudaGetSymbolAddress((void**)&xh,   g_xh);
    cudaGetSymbolAddress((void**)&qkh,  g_qkh);
    cudaGetSymbolAddress((void**)&valh, g_valh);
    cudaGetSymbolAddress((void**)&keyh, g_keyh);
    cudaGetSymbolAddress((void**)&vpsp, g_vpsp);
    cudaGetSymbolAddress((void**)&sh,   g_sh);
    cudaGetSymbolAddress((void**)&ph,   g_ph);
    cudaGetSymbolAddress((void**)&yh,   g_yh);
    cudaGetSymbolAddress((void**)&wq,   g_wq);
    cudaGetSymbolAddress((void**)&wv,   g_wv);
    cudaGetSymbolAddress((void**)&wo,   g_wo);

    cudaFuncSetAttribute(gemm_kernel<true, true, true, false, true>,
                         cudaFuncAttributeMaxDynamicSharedMemorySize, GEMM_SMEM);
    cudaFuncSetAttribute(gemm_kernel<false, false, false, false, true>,
                         cudaFuncAttributeMaxDynamicSharedMemorySize, GEMM_SMEM);
    cudaFuncSetAttribute(gemm_kernel<false, true, false, true, false>,
                         cudaFuncAttributeMaxDynamicSharedMemorySize, GEMM_SMEM);
    cudaFuncSetAttribute(attn_out_kernel,
                         cudaFuncAttributeMaxDynamicSharedMemorySize, AO_SMEM);

    // 0) fp16 conversions
    cvt_weights_kernel<<<(CV*CIN + 255) / 256, 256>>>(qk_w, v_w, out_w, wq, wv, wo);
    cvt_half_v8_kernel<<<(BB*CIN*HW/8 + 255) / 256, 256>>>(
        (const float4*)x, (uint4*)xh, BB*CIN*HW/8);

    // 1+2) fused: qk = relu(bn(conv(x,wq))), val = relu(bn(conv(x,wv)))
    gemm_kernel<true, true, true, false, true><<<dim3(32, 6, BB), 256, GEMM_SMEM>>>(
        wq, 0, xh, (size_t)CIN*HW, qk_gamma, qk_beta, qk_mean, qk_var,
        1.f, nullptr, qkh, (size_t)CK*HW, CIN,
        wv, v_gamma, v_beta, v_mean, v_var, valh, (size_t)CV*HW);
    // 3) key = psp(qk) [s][c]; value = psp(val) [c][s]
    psp_kernel<<<BB * CK, 128>>>(qkh,  keyh, CK, 1);
    psp_kernel<<<BB * CV, 128>>>(valh, vpsp, CV, 0);
    // 4) raw scores [s][n] = (key @ qk) / 16
    gemm_kernel<false, false, false, false, true><<<dim3(32, 1, BB), 256, GEMM_SMEM>>>(
        keyh, (size_t)128*CK, qkh, (size_t)CK*HW, nullptr, nullptr, nullptr, nullptr,
        0.0625f, nullptr, sh, (size_t)128*HW, CK,
        nullptr, nullptr, nullptr, nullptr, nullptr, nullptr, 0);
    // 5) column softmax -> p [s][n] half
    softmax_kernel<<<dim3(32, BB), 128>>>(sh, ph);
    // 6) y[c][n] = value[c][s] @ p[s][n]
    attn_out_kernel<<<dim3(32, 4, BB), 256, AO_SMEM>>>(vpsp, ph, yh);
    // 7) out = x + bn(conv(y, wo))
    gemm_kernel<false, true, false, true, false><<<dim3(32, 4, BB), 256, GEMM_SMEM>>>(
        wo, 0, yh, (size_t)CV*HW, o_gamma, o_beta, o_mean, o_var,
        1.f, x, out, (size_t)CIN*HW, CV,
        nullptr, nullptr, nullptr, nullptr, nullptr, nullptr, 0);
}

// round 7
// speedup vs baseline: 4.9932x; 1.8622x over previous
#include <cuda_runtime.h>
#include <cuda_fp16.h>
#include <cstdint>
#include <math.h>

#define BB   8
#define CIN  512
#define CK   256
#define CV   512
#define HW   4096
#define SS   110

// Scratch (__device__ globals are zero-initialized; pad regions never written
// stay zero -> free zero-padding).
__device__ __align__(16) __half g_xh    [BB*CIN*HW];    // [b][k][n]
__device__ __align__(16) __half g_qkh   [BB*CK*HW];     // [b][c][n]
__device__ __align__(16) __half g_valh  [BB*CV*HW];     // [b][c][n]
__device__ __align__(16) __half g_keyh  [BB*128*CK];    // [b][s(pad128)][c]
__device__ __align__(16) __half g_vpsp  [BB*CV*112];    // [b][c][s(pad112)]
__device__ __align__(16) __half g_sh    [BB*128*HW];    // [b][s(pad128)][n]
__device__ __align__(16) __half g_ph    [BB*112*HW];    // [b][s(pad112)][n]
__device__ __align__(16) __half g_yh    [BB*CV*HW];     // [b][c][n]
__device__ __align__(16) __half g_wq    [CK*CIN];
__device__ __align__(16) __half g_wv    [CV*CIN];
__device__ __align__(16) __half g_wo    [CIN*CV];

// ---------------------------------------------------------------------------
__device__ __forceinline__ uint32_t smem_u32(const void* p) {
    uint32_t a;
    asm("{ .reg .u64 t; cvta.to.shared.u64 t, %1; cvt.u32.u64 %0, t; }" : "=r"(a) : "l"(p));
    return a;
}
__device__ __forceinline__ void ldsm_x4(uint32_t* r, uint32_t addr) {
    asm volatile("ldmatrix.sync.aligned.m8n8.x4.shared.b16 {%0,%1,%2,%3}, [%4];"
        : "=r"(r[0]), "=r"(r[1]), "=r"(r[2]), "=r"(r[3]) : "r"(addr));
}
__device__ __forceinline__ void ldsm_x4_t(uint32_t* r, uint32_t addr) {
    asm volatile("ldmatrix.sync.aligned.m8n8.x4.trans.shared.b16 {%0,%1,%2,%3}, [%4];"
        : "=r"(r[0]), "=r"(r[1]), "=r"(r[2]), "=r"(r[3]) : "r"(addr));
}
__device__ __forceinline__ void mma_f16(float* c, const uint32_t* a, const uint32_t* b) {
    asm volatile(
        "mma.sync.aligned.m16n8k16.row.col.f32.f16.f16.f32 "
        "{%0,%1,%2,%3}, {%4,%5,%6,%7}, {%8,%9}, {%0,%1,%2,%3};"
        : "+f"(c[0]), "+f"(c[1]), "+f"(c[2]), "+f"(c[3])
        : "r"(a[0]), "r"(a[1]), "r"(a[2]), "r"(a[3]), "r"(b[0]), "r"(b[1]));
}
__device__ __forceinline__ void cpa16(uint32_t dst, const void* src) {
    asm volatile("cp.async.cg.shared.global [%0], [%1], 16;" :: "r"(dst), "l"(src));
}

// ---------------------------------------------------------------------------
// Generalized GEMM: out[b,m,n] = epi( sum_k A[m,k] * B[b,k,n] )
// CTA 128m x 128n, 8 warps (2x4), warp 64x32. K staged 32, 4-stage pipeline.
// FUSED: blockIdx.y<2 -> branch 1 (A,params,out), else branch 2.
// ---------------------------------------------------------------------------
#define A_STRH 40
#define B_STRH 136
#define A_STG  (128*A_STRH*2)              // 10240 B
#define B_STG  (32*B_STRH*2)               // 8704 B
#define STG    (A_STG + B_STG)             // 18944 B
#define NSTAGE 4
#define GEMM_SMEM (NSTAGE*STG)             // 75776 B

template<bool FUSED, bool BN, bool RELU, bool RESID, bool HALF_OUT>
__global__ __launch_bounds__(256, 2) void gemm_kernel(
    const __half* __restrict__ A, size_t a_bstride,
    const __half* __restrict__ Bm, size_t b_bstride,
    const float* __restrict__ gamma, const float* __restrict__ beta,
    const float* __restrict__ mean,  const float* __restrict__ var,
    float uscale,
    const float* __restrict__ resid,
    void* __restrict__ outp, size_t o_bstride,
    int Ktot,
    // FUSED branch-2 args
    const __half* __restrict__ A2,
    const float* __restrict__ gamma2, const float* __restrict__ beta2,
    const float* __restrict__ mean2,  const float* __restrict__ var2,
    void* __restrict__ outp2, size_t o_bstride2)
{
    extern __shared__ __align__(16) char smc[];
    const uint32_t sb = smem_u32(smc);
    const int tid = threadIdx.x, lane = tid & 31, wid = tid >> 5;
    const int gidr = lane >> 2, t4 = lane & 3;
    const int wm = wid >> 2, wn = wid & 3;
    const int n0 = blockIdx.x * 128, b = blockIdx.z;
    const int NK = Ktot >> 5;

    int m0 = blockIdx.y * 128;
    const __half* Ause = A;
    const float *g_ = gamma, *be_ = beta, *me_ = mean, *va_ = var;
    void* ouse = outp;
    size_t ostr = o_bstride;
    if (FUSED && blockIdx.y >= 2) {
        m0 = (blockIdx.y - 2) * 128;
        Ause = A2; g_ = gamma2; be_ = beta2; me_ = mean2; va_ = var2;
        ouse = outp2; ostr = o_bstride2;
    }

    const __half* gA = Ause + (size_t)b * a_bstride + (size_t)m0 * Ktot;
    const __half* gB = Bm + (size_t)b * b_bstride + n0;

    auto load_stage = [&](int s) {
        const uint32_t base = sb + (uint32_t)(s & (NSTAGE-1)) * STG;
        #pragma unroll
        for (int it = 0; it < 2; ++it) {            // A: 128r x 4 chunks
            int idx = it * 256 + tid;
            int r = idx >> 2, c = idx & 3;
            cpa16(base + (uint32_t)(r * A_STRH + c * 8) * 2,
                  gA + (size_t)r * Ktot + s * 32 + c * 8);
        }
        #pragma unroll
        for (int it = 0; it < 2; ++it) {            // B: 32r x 16 chunks
            int idx = it * 256 + tid;
            int r = idx >> 4, c = idx & 15;
            cpa16(base + A_STG + (uint32_t)(r * B_STRH + c * 8) * 2,
                  gB + (size_t)(s * 32 + r) * HW + c * 8);
        }
        asm volatile("cp.async.commit_group;" ::: "memory");
    };

    float acc[4][4][4];
    #pragma unroll
    for (int mt = 0; mt < 4; ++mt)
        #pragma unroll
        for (int nt = 0; nt < 4; ++nt)
            #pragma unroll
            for (int r = 0; r < 4; ++r) acc[mt][nt][r] = 0.f;

    for (int s = 0; s < NSTAGE - 1 && s < NK; ++s) load_stage(s);
    asm volatile("cp.async.wait_group 2;" ::: "memory");
    __syncthreads();

    const int a_row = lane & 15, a_koff = (lane >> 4) * 8;
    const int b_krow = ((lane >> 3) & 1) * 8 + (lane & 7);
    const int b_noff = (lane >> 4) * 8;

    for (int kt = 0; kt < NK; ++kt) {
        if (kt + NSTAGE - 1 < NK) load_stage(kt + NSTAGE - 1);
        else asm volatile("cp.async.commit_group;" ::: "memory");

        const uint32_t sA = sb + (uint32_t)(kt & (NSTAGE-1)) * STG;
        const uint32_t sB = sA + A_STG;
        #pragma unroll
        for (int s16 = 0; s16 < 2; ++s16) {
            const int kk = s16 * 16;
            uint32_t af[4][4], bf[4][2];
            #pragma unroll
            for (int mt = 0; mt < 4; ++mt) {
                int row = wm * 64 + mt * 16 + a_row;
                ldsm_x4(af[mt], sA + (uint32_t)(row * A_STRH + kk + a_koff) * 2);
            }
            #pragma unroll
            for (int nt2 = 0; nt2 < 2; ++nt2) {
                uint32_t r4[4];
                int ncol = wn * 32 + nt2 * 16 + b_noff;
                ldsm_x4_t(r4, sB + (uint32_t)((kk + b_krow) * B_STRH + ncol) * 2);
                bf[nt2*2][0] = r4[0]; bf[nt2*2][1] = r4[1];
                bf[nt2*2+1][0] = r4[2]; bf[nt2*2+1][1] = r4[3];
            }
            #pragma unroll
            for (int mt = 0; mt < 4; ++mt)
                #pragma unroll
                for (int nt = 0; nt < 4; ++nt)
                    mma_f16(acc[mt][nt], af[mt], bf[nt]);
        }
        asm volatile("cp.async.wait_group 2;" ::: "memory");
        __syncthreads();
    }

    // Epilogue
    #pragma unroll
    for (int mt = 0; mt < 4; ++mt) {
        const int ml = m0 + wm * 64 + mt * 16 + gidr;
        const int mh = ml + 8;
        float scl, ttl, sch, tth;
        if (BN) {
            scl = g_[ml] * rsqrtf(va_[ml] + 1e-5f);
            ttl = be_[ml] - me_[ml] * scl;
            sch = g_[mh] * rsqrtf(va_[mh] + 1e-5f);
            tth = be_[mh] - me_[mh] * sch;
        } else { scl = uscale; ttl = 0.f; sch = uscale; tth = 0.f; }
        #pragma unroll
        for (int nt = 0; nt < 4; ++nt) {
            const int nn = n0 + wn * 32 + nt * 8 + 2 * t4;
            float2 vl, vh;
            vl.x = acc[mt][nt][0] * scl + ttl;
            vl.y = acc[mt][nt][1] * scl + ttl;
            vh.x = acc[mt][nt][2] * sch + tth;
            vh.y = acc[mt][nt][3] * sch + tth;
            if (RELU) {
                vl.x = fmaxf(vl.x, 0.f); vl.y = fmaxf(vl.y, 0.f);
                vh.x = fmaxf(vh.x, 0.f); vh.y = fmaxf(vh.y, 0.f);
            }
            if (HALF_OUT) {
                __half* oh = (__half*)ouse + (size_t)b * ostr;
                *(__half2*)(oh + (size_t)ml * HW + nn) = __floats2half2_rn(vl.x, vl.y);
                *(__half2*)(oh + (size_t)mh * HW + nn) = __floats2half2_rn(vh.x, vh.y);
            } else {
                float* of = (float*)ouse + (size_t)b * ostr;
                if (RESID) {
                    const float* rp = resid + (size_t)b * ostr;
                    float2 rl = *(const float2*)(rp + (size_t)ml * HW + nn);
                    float2 rh = *(const float2*)(rp + (size_t)mh * HW + nn);
                    vl.x += rl.x; vl.y += rl.y; vh.x += rh.x; vh.y += rh.y;
                }
                *(float2*)(of + (size_t)ml * HW + nn) = vl;
                *(float2*)(of + (size_t)mh * HW + nn) = vh;
            }
        }
    }
}

// ---------------------------------------------------------------------------
// attn_out: y[b][c][n] = sum_s Vp[b][c][s] * P[b][s][n]  (K=112 single shot)
// ---------------------------------------------------------------------------
#define AO_ASTR 120
#define AO_SMEM (128*AO_ASTR*2 + 112*B_STRH*2)   // 61184

__global__ __launch_bounds__(256, 2) void attn_out_kernel(
    const __half* __restrict__ Vp, const __half* __restrict__ P, __half* __restrict__ y)
{
    extern __shared__ __align__(16) char smc[];
    const uint32_t sb = smem_u32(smc);
    const uint32_t sA = sb, sB = sb + 128*AO_ASTR*2;
    const int tid = threadIdx.x, lane = tid & 31, wid = tid >> 5;
    const int gidr = lane >> 2, t4 = lane & 3;
    const int wm = wid >> 2, wn = wid & 3;
    const int n0 = blockIdx.x * 128, c0 = blockIdx.y * 128, b = blockIdx.z;

    const __half* gA = Vp + (size_t)b * CV * 112 + (size_t)c0 * 112;
    const __half* gB = P + (size_t)b * 112 * HW + n0;

    #pragma unroll
    for (int it = 0; it < 7; ++it) {
        int idx = it * 256 + tid;
        int r = idx / 14, c = idx - r * 14;
        cpa16(sA + (uint32_t)(r * AO_ASTR + c * 8) * 2, gA + (size_t)r * 112 + c * 8);
    }
    #pragma unroll
    for (int it = 0; it < 7; ++it) {
        int idx = it * 256 + tid;
        int r = idx >> 4, c = idx & 15;
        cpa16(sB + (uint32_t)(r * B_STRH + c * 8) * 2, gB + (size_t)r * HW + c * 8);
    }
    asm volatile("cp.async.commit_group;\ncp.async.wait_group 0;" ::: "memory");
    __syncthreads();

    const int a_row = lane & 15, a_koff = (lane >> 4) * 8;
    const int b_krow = ((lane >> 3) & 1) * 8 + (lane & 7);
    const int b_noff = (lane >> 4) * 8;

    float acc[4][4][4];
    #pragma unroll
    for (int mt = 0; mt < 4; ++mt)
        #pragma unroll
        for (int nt = 0; nt < 4; ++nt)
            #pragma unroll
            for (int r = 0; r < 4; ++r) acc[mt][nt][r] = 0.f;

    #pragma unroll
    for (int s16 = 0; s16 < 7; ++s16) {
        const int kk = s16 * 16;
        uint32_t af[4][4], bf[4][2];
        #pragma unroll
        for (int mt = 0; mt < 4; ++mt) {
            int row = wm * 64 + mt * 16 + a_row;
            ldsm_x4(af[mt], sA + (uint32_t)(row * AO_ASTR + kk + a_koff) * 2);
        }
        #pragma unroll
        for (int nt2 = 0; nt2 < 2; ++nt2) {
            uint32_t r4[4];
            int ncol = wn * 32 + nt2 * 16 + b_noff;
            ldsm_x4_t(r4, sB + (uint32_t)((kk + b_krow) * B_STRH + ncol) * 2);
            bf[nt2*2][0] = r4[0]; bf[nt2*2][1] = r4[1];
            bf[nt2*2+1][0] = r4[2]; bf[nt2*2+1][1] = r4[3];
        }
        #pragma unroll
        for (int mt = 0; mt < 4; ++mt)
            #pragma unroll
            for (int nt = 0; nt < 4; ++nt)
                mma_f16(acc[mt][nt], af[mt], bf[nt]);
    }

    __half* yb = y + (size_t)b * CV * HW;
    #pragma unroll
    for (int mt = 0; mt < 4; ++mt) {
        const int ml = c0 + wm * 64 + mt * 16 + gidr;
        #pragma unroll
        for (int nt = 0; nt < 4; ++nt) {
            const int nn = n0 + wn * 32 + nt * 8 + 2 * t4;
            *(__half2*)(yb + (size_t)ml * HW + nn) =
                __floats2half2_rn(acc[mt][nt][0], acc[mt][nt][1]);
            *(__half2*)(yb + (size_t)(ml + 8) * HW + nn) =
                __floats2half2_rn(acc[mt][nt][2], acc[mt][nt][3]);
        }
    }
}

// ---------------------------------------------------------------------------
// Weight + x fp16 conversions
// ---------------------------------------------------------------------------
__global__ __launch_bounds__(256) void cvt_weights_kernel(
    const float* __restrict__ wq, const float* __restrict__ wv,
    const float* __restrict__ wo,
    __half* __restrict__ oq, __half* __restrict__ ov, __half* __restrict__ oo)
{
    int i = blockIdx.x * 256 + threadIdx.x;
    if (i < CK*CIN) oq[i] = __float2half_rn(wq[i]);
    if (i < CV*CIN) { ov[i] = __float2half_rn(wv[i]); oo[i] = __float2half_rn(wo[i]); }
}
__global__ __launch_bounds__(256) void cvt_half_v8_kernel(
    const float4* __restrict__ a, uint4* __restrict__ o, int n8)
{
    int i = blockIdx.x * 256 + threadIdx.x;
    if (i < n8) {
        float4 f0 = a[2*i], f1 = a[2*i+1];
        __half2 h0 = __floats2half2_rn(f0.x, f0.y);
        __half2 h1 = __floats2half2_rn(f0.z, f0.w);
        __half2 h2 = __floats2half2_rn(f1.x, f1.y);
        __half2 h3 = __floats2half2_rn(f1.z, f1.w);
        uint4 u;
        u.x = *(uint32_t*)&h0; u.y = *(uint32_t*)&h1;
        u.z = *(uint32_t*)&h2; u.w = *(uint32_t*)&h3;
        o[i] = u;
    }
}

// ---------------------------------------------------------------------------
// PSP adaptive max pool, half in / half out. Conflict-free smem (stride 65)
// and 2 planes per 256-thread block.
// mode 0: out[(b*C + c)*112 + cell]   (value: [c][s] pad 112)
// mode 1: out[(b*128 + cell)*C + c]   (key:   [s pad128][c])
// ---------------------------------------------------------------------------
#define SP_STR 65
#define RM_STR 65

__global__ __launch_bounds__(256) void psp_kernel(
    const __half* __restrict__ in, __half* __restrict__ out, int C, int mode)
{
    __shared__ __align__(16) float sp[2][64 * SP_STR];   // 33280 B
    __shared__ float rm[2][17 * RM_STR];                 //  8840 B
    __shared__ float s8v[2][64];
    const int pl = threadIdx.x >> 7;          // which plane (0/1)
    const int tid = threadIdx.x & 127;
    const int bc = blockIdx.x * 2 + pl;
    const int b = bc / C, c = bc - b * C;
    float* spp = sp[pl];
    float* rmp = rm[pl];
    const __half* plane = in + (size_t)bc * 4096;

    // Load + widen to fp32, stride-65 rows (conflict-free stores)
    for (int i = tid; i < 512; i += 128) {
        uint4 u = ((const uint4*)plane)[i];
        __half2* h = (__half2*)&u;
        int row = i >> 3, col = (i & 7) * 8;
        float* d = spp + row * SP_STR + col;
        float2 f0 = __half22float2(h[0]), f1 = __half22float2(h[1]);
        float2 f2 = __half22float2(h[2]), f3 = __half22float2(h[3]);
        d[0]=f0.x; d[1]=f0.y; d[2]=f1.x; d[3]=f1.y;
        d[4]=f2.x; d[5]=f2.y; d[6]=f3.x; d[7]=f3.y;
    }
    __syncthreads();

    // Phase 1: per-(seg,row) column-range maxes. Warp has uniform seg,
    // consecutive rows -> banks (row + cc) mod 32 distinct: conflict-free.
    const int cs[17] = {0,21,42, 0,10,21,32,42,53, 0,8,16,24,32,40,48,56};
    const int ce[17] = {22,43,64, 11,22,32,43,54,64, 8,16,24,32,40,48,56,64};
    for (int idx = tid; idx < 17 * 64; idx += 128) {
        int seg = idx >> 6, row = idx & 63;
        const float* rp = spp + row * SP_STR;
        float m = -3.402823e38f;
        for (int cc = cs[seg]; cc < ce[seg]; ++cc) m = fmaxf(m, rp[cc]);
        rmp[seg * RM_STR + row] = m;
    }
    __syncthreads();

    // Phase 2: cells (rm stride 65 -> s=8 reads conflict-free)
    float m = -3.402823e38f;
    int cell = -1;
    if (tid < 64) {                        // s=8
        int i = tid >> 3, j = tid & 7;
        for (int r = i * 8; r < i * 8 + 8; ++r) m = fmaxf(m, rmp[(9 + j) * RM_STR + r]);
        s8v[pl][tid] = m; cell = 46 + tid;
    } else if (tid < 100) {                // s=6
        const int st[6] = {0,10,21,32,42,53}, en[6] = {11,22,32,43,54,64};
        int t = tid - 64, i = t / 6, j = t - i * 6;
        for (int r = st[i]; r < en[i]; ++r) m = fmaxf(m, rmp[(3 + j) * RM_STR + r]);
        cell = 10 + t;
    } else if (tid < 109) {                // s=3
        const int st[3] = {0,21,42}, en[3] = {22,43,64};
        int t = tid - 100, i = t / 3, j = t - i * 3;
        for (int r = st[i]; r < en[i]; ++r) m = fmaxf(m, rmp[j * RM_STR + r]);
        cell = 1 + t;
    }
    if (cell >= 0) {
        size_t o = mode ? ((size_t)(b * 128 + cell) * C + c)
                        : ((size_t)bc * 112 + cell);
        out[o] = __float2half_rn(m);
    }
    __syncthreads();
    if (tid == 0) {                        // s=1 from the 64 exact 8x8 cells
        float mm = s8v[pl][0];
        for (int i = 1; i < 64; ++i) mm = fmaxf(mm, s8v[pl][i]);
        size_t o = mode ? ((size_t)(b * 128) * C + c) : ((size_t)bc * 112);
        out[o] = __float2half_rn(mm);
    }
}

// ---------------------------------------------------------------------------
// Column softmax over s (110) for each n.
// ---------------------------------------------------------------------------
__global__ __launch_bounds__(128) void softmax_kernel(
    const __half* __restrict__ s_h, __half* __restrict__ p_h)
{
    __shared__ __align__(16) __half ss[SS * 128];
    const int b = blockIdx.y, n0 = blockIdx.x * 128;
    const int tid = threadIdx.x;
    const __half* sbx = s_h + (size_t)b * 128 * HW + n0;
    for (int i = tid; i < SS * 16; i += 128) {
        int row = i >> 4, col = (i & 15) * 8;
        *(uint4*)&ss[row * 128 + col] = *(const uint4*)&sbx[(size_t)row * HW + col];
    }
    __syncthreads();

    float mx = -3.402823e38f;
    #pragma unroll 2
    for (int s = 0; s < SS; ++s) mx = fmaxf(mx, __half2float(ss[s * 128 + tid]));
    float sum = 0.f;
    #pragma unroll 2
    for (int s = 0; s < SS; ++s) sum += __expf(__half2float(ss[s * 128 + tid]) - mx);
    const float inv = 1.f / sum;
    __half* pb = p_h + (size_t)b * 112 * HW + n0 + tid;
    #pragma unroll 2
    for (int s = 0; s < SS; ++s)
        pb[(size_t)s * HW] = __float2half_rn(__expf(__half2float(ss[s * 128 + tid]) - mx) * inv);
}

// ---------------------------------------------------------------------------
extern "C" void kernel_launch(void* const* d_in, const int* in_sizes, int n_in,
                              void* d_out, int out_size)
{
    const float* x        = (const float*)d_in[0];
    const float* qk_w     = (const float*)d_in[1];
    const float* qk_gamma = (const float*)d_in[2];
    const float* qk_beta  = (const float*)d_in[3];
    const float* qk_mean  = (const float*)d_in[4];
    const float* qk_var   = (const float*)d_in[5];
    const float* v_w      = (const float*)d_in[6];
    const float* v_gamma  = (const float*)d_in[7];
    const float* v_beta   = (const float*)d_in[8];
    const float* v_mean   = (const float*)d_in[9];
    const float* v_var    = (const float*)d_in[10];
    const float* out_w    = (const float*)d_in[11];
    const float* o_gamma  = (const float*)d_in[12];
    const float* o_beta   = (const float*)d_in[13];
    const float* o_mean   = (const float*)d_in[14];
    const float* o_var    = (const float*)d_in[15];
    float* out = (float*)d_out;

    __half *xh, *qkh, *valh, *keyh, *vpsp, *sh, *ph, *yh, *wq, *wv, *wo;
    cudaGetSymbolAddress((void**)&xh,   g_xh);
    cudaGetSymbolAddress((void**)&qkh,  g_qkh);
    cudaGetSymbolAddress((void**)&valh, g_valh);
    cudaGetSymbolAddress((void**)&keyh, g_keyh);
    cudaGetSymbolAddress((void**)&vpsp, g_vpsp);
    cudaGetSymbolAddress((void**)&sh,   g_sh);
    cudaGetSymbolAddress((void**)&ph,   g_ph);
    cudaGetSymbolAddress((void**)&yh,   g_yh);
    cudaGetSymbolAddress((void**)&wq,   g_wq);
    cudaGetSymbolAddress((void**)&wv,   g_wv);
    cudaGetSymbolAddress((void**)&wo,   g_wo);

    cudaFuncSetAttribute(gemm_kernel<true, true, true, false, true>,
                         cudaFuncAttributeMaxDynamicSharedMemorySize, GEMM_SMEM);
    cudaFuncSetAttribute(gemm_kernel<false, false, false, false, true>,
                         cudaFuncAttributeMaxDynamicSharedMemorySize, GEMM_SMEM);
    cudaFuncSetAttribute(gemm_kernel<false, true, false, true, false>,
                         cudaFuncAttributeMaxDynamicSharedMemorySize, GEMM_SMEM);
    cudaFuncSetAttribute(attn_out_kernel,
                         cudaFuncAttributeMaxDynamicSharedMemorySize, AO_SMEM);

    // 0) fp16 conversions
    cvt_weights_kernel<<<(CV*CIN + 255) / 256, 256>>>(qk_w, v_w, out_w, wq, wv, wo);
    cvt_half_v8_kernel<<<(BB*CIN*HW/8 + 255) / 256, 256>>>(
        (const float4*)x, (uint4*)xh, BB*CIN*HW/8);

    // 1+2) fused: qk = relu(bn(conv(x,wq))), val = relu(bn(conv(x,wv)))
    gemm_kernel<true, true, true, false, true><<<dim3(32, 6, BB), 256, GEMM_SMEM>>>(
        wq, 0, xh, (size_t)CIN*HW, qk_gamma, qk_beta, qk_mean, qk_var,
        1.f, nullptr, qkh, (size_t)CK*HW, CIN,
        wv, v_gamma, v_beta, v_mean, v_var, valh, (size_t)CV*HW);
    // 3) key = psp(qk) [s][c]; value = psp(val) [c][s]
    psp_kernel<<<BB * CK / 2, 256>>>(qkh,  keyh, CK, 1);
    psp_kernel<<<BB * CV / 2, 256>>>(valh, vpsp, CV, 0);
    // 4) raw scores [s][n] = (key @ qk) / 16
    gemm_kernel<false, false, false, false, true><<<dim3(32, 1, BB), 256, GEMM_SMEM>>>(
        keyh, (size_t)128*CK, qkh, (size_t)CK*HW, nullptr, nullptr, nullptr, nullptr,
        0.0625f, nullptr, sh, (size_t)128*HW, CK,
        nullptr, nullptr, nullptr, nullptr, nullptr, nullptr, 0);
    // 5) column softmax -> p [s][n] half
    softmax_kernel<<<dim3(32, BB), 128>>>(sh, ph);
    // 6) y[c][n] = value[c][s] @ p[s][n]
    attn_out_kernel<<<dim3(32, 4, BB), 256, AO_SMEM>>>(vpsp, ph, yh);
    // 7) out = x + bn(conv(y, wo))
    gemm_kernel<false, true, false, true, false><<<dim3(32, 4, BB), 256, GEMM_SMEM>>>(
        wo, 0, yh, (size_t)CV*HW, o_gamma, o_beta, o_mean, o_var,
        1.f, x, out, (size_t)CIN*HW, CV,
        nullptr, nullptr, nullptr, nullptr, nullptr, nullptr, 0);
}

// round 8
// speedup vs baseline: 5.1702x; 1.0354x over previous
#include <cuda_runtime.h>
#include <cuda_fp16.h>
#include <cstdint>
#include <math.h>

#define BB   8
#define CIN  512
#define CK   256
#define CV   512
#define HW   4096
#define SS   110

// Scratch (__device__ globals are zero-initialized; pad regions never written
// stay zero -> free zero-padding).
__device__ __align__(16) __half g_xh    [BB*CIN*HW];    // [b][k][n]
__device__ __align__(16) __half g_qkh   [BB*CK*HW];     // [b][c][n]
__device__ __align__(16) __half g_valh  [BB*CV*HW];     // [b][c][n]
__device__ __align__(16) __half g_keyh  [BB*128*CK];    // [b][s(pad128)][c]
__device__ __align__(16) __half g_vpsp  [BB*CV*112];    // [b][c][s(pad112)]
__device__ __align__(16) __half g_sh    [BB*128*HW];    // [b][s(pad128)][n]
__device__ __align__(16) __half g_ph    [BB*112*HW];    // [b][s(pad112)][n]
__device__ __align__(16) __half g_yh    [BB*CV*HW];     // [b][c][n]
__device__ __align__(16) __half g_wq    [CK*CIN];
__device__ __align__(16) __half g_wv    [CV*CIN];
__device__ __align__(16) __half g_wo    [CIN*CV];

// ---------------------------------------------------------------------------
__device__ __forceinline__ uint32_t smem_u32(const void* p) {
    uint32_t a;
    asm("{ .reg .u64 t; cvta.to.shared.u64 t, %1; cvt.u32.u64 %0, t; }" : "=r"(a) : "l"(p));
    return a;
}
__device__ __forceinline__ void ldsm_x4(uint32_t* r, uint32_t addr) {
    asm volatile("ldmatrix.sync.aligned.m8n8.x4.shared.b16 {%0,%1,%2,%3}, [%4];"
        : "=r"(r[0]), "=r"(r[1]), "=r"(r[2]), "=r"(r[3]) : "r"(addr));
}
__device__ __forceinline__ void ldsm_x4_t(uint32_t* r, uint32_t addr) {
    asm volatile("ldmatrix.sync.aligned.m8n8.x4.trans.shared.b16 {%0,%1,%2,%3}, [%4];"
        : "=r"(r[0]), "=r"(r[1]), "=r"(r[2]), "=r"(r[3]) : "r"(addr));
}
__device__ __forceinline__ void mma_f16(float* c, const uint32_t* a, const uint32_t* b) {
    asm volatile(
        "mma.sync.aligned.m16n8k16.row.col.f32.f16.f16.f32 "
        "{%0,%1,%2,%3}, {%4,%5,%6,%7}, {%8,%9}, {%0,%1,%2,%3};"
        : "+f"(c[0]), "+f"(c[1]), "+f"(c[2]), "+f"(c[3])
        : "r"(a[0]), "r"(a[1]), "r"(a[2]), "r"(a[3]), "r"(b[0]), "r"(b[1]));
}
__device__ __forceinline__ void cpa16(uint32_t dst, const void* src) {
    asm volatile("cp.async.cg.shared.global [%0], [%1], 16;" :: "r"(dst), "l"(src));
}

// ---------------------------------------------------------------------------
// Generalized GEMM: out[b,m,n] = epi( sum_k A[m,k] * B[b,k,n] )
// CTA 128m x 128n, 8 warps (2x4), warp 64x32. K staged 32, 4-stage pipeline.
// FUSED: blockIdx.y<2 -> branch 1 (A,params,out), else branch 2.
// ---------------------------------------------------------------------------
#define A_STRH 40
#define B_STRH 136
#define A_STG  (128*A_STRH*2)              // 10240 B
#define B_STG  (32*B_STRH*2)               // 8704 B
#define STG    (A_STG + B_STG)             // 18944 B
#define NSTAGE 4
#define GEMM_SMEM (NSTAGE*STG)             // 75776 B

template<bool FUSED, bool BN, bool RELU, bool RESID, bool HALF_OUT>
__global__ __launch_bounds__(256, 2) void gemm_kernel(
    const __half* __restrict__ A, size_t a_bstride,
    const __half* __restrict__ Bm, size_t b_bstride,
    const float* __restrict__ gamma, const float* __restrict__ beta,
    const float* __restrict__ mean,  const float* __restrict__ var,
    float uscale,
    const float* __restrict__ resid,
    void* __restrict__ outp, size_t o_bstride,
    int Ktot,
    // FUSED branch-2 args
    const __half* __restrict__ A2,
    const float* __restrict__ gamma2, const float* __restrict__ beta2,
    const float* __restrict__ mean2,  const float* __restrict__ var2,
    void* __restrict__ outp2, size_t o_bstride2)
{
    extern __shared__ __align__(16) char smc[];
    const uint32_t sb = smem_u32(smc);
    const int tid = threadIdx.x, lane = tid & 31, wid = tid >> 5;
    const int gidr = lane >> 2, t4 = lane & 3;
    const int wm = wid >> 2, wn = wid & 3;
    const int n0 = blockIdx.x * 128, b = blockIdx.z;
    const int NK = Ktot >> 5;

    int m0 = blockIdx.y * 128;
    const __half* Ause = A;
    const float *g_ = gamma, *be_ = beta, *me_ = mean, *va_ = var;
    void* ouse = outp;
    size_t ostr = o_bstride;
    if (FUSED && blockIdx.y >= 2) {
        m0 = (blockIdx.y - 2) * 128;
        Ause = A2; g_ = gamma2; be_ = beta2; me_ = mean2; va_ = var2;
        ouse = outp2; ostr = o_bstride2;
    }

    const __half* gA = Ause + (size_t)b * a_bstride + (size_t)m0 * Ktot;
    const __half* gB = Bm + (size_t)b * b_bstride + n0;

    auto load_stage = [&](int s) {
        const uint32_t base = sb + (uint32_t)(s & (NSTAGE-1)) * STG;
        #pragma unroll
        for (int it = 0; it < 2; ++it) {            // A: 128r x 4 chunks
            int idx = it * 256 + tid;
            int r = idx >> 2, c = idx & 3;
            cpa16(base + (uint32_t)(r * A_STRH + c * 8) * 2,
                  gA + (size_t)r * Ktot + s * 32 + c * 8);
        }
        #pragma unroll
        for (int it = 0; it < 2; ++it) {            // B: 32r x 16 chunks
            int idx = it * 256 + tid;
            int r = idx >> 4, c = idx & 15;
            cpa16(base + A_STG + (uint32_t)(r * B_STRH + c * 8) * 2,
                  gB + (size_t)(s * 32 + r) * HW + c * 8);
        }
        asm volatile("cp.async.commit_group;" ::: "memory");
    };

    float acc[4][4][4];
    #pragma unroll
    for (int mt = 0; mt < 4; ++mt)
        #pragma unroll
        for (int nt = 0; nt < 4; ++nt)
            #pragma unroll
            for (int r = 0; r < 4; ++r) acc[mt][nt][r] = 0.f;

    for (int s = 0; s < NSTAGE - 1 && s < NK; ++s) load_stage(s);
    asm volatile("cp.async.wait_group 2;" ::: "memory");
    __syncthreads();

    const int a_row = lane & 15, a_koff = (lane >> 4) * 8;
    const int b_krow = ((lane >> 3) & 1) * 8 + (lane & 7);
    const int b_noff = (lane >> 4) * 8;

    for (int kt = 0; kt < NK; ++kt) {
        if (kt + NSTAGE - 1 < NK) load_stage(kt + NSTAGE - 1);
        else asm volatile("cp.async.commit_group;" ::: "memory");

        const uint32_t sA = sb + (uint32_t)(kt & (NSTAGE-1)) * STG;
        const uint32_t sB = sA + A_STG;
        #pragma unroll
        for (int s16 = 0; s16 < 2; ++s16) {
            const int kk = s16 * 16;
            uint32_t af[4][4], bf[4][2];
            #pragma unroll
            for (int mt = 0; mt < 4; ++mt) {
                int row = wm * 64 + mt * 16 + a_row;
                ldsm_x4(af[mt], sA + (uint32_t)(row * A_STRH + kk + a_koff) * 2);
            }
            #pragma unroll
            for (int nt2 = 0; nt2 < 2; ++nt2) {
                uint32_t r4[4];
                int ncol = wn * 32 + nt2 * 16 + b_noff;
                ldsm_x4_t(r4, sB + (uint32_t)((kk + b_krow) * B_STRH + ncol) * 2);
                bf[nt2*2][0] = r4[0]; bf[nt2*2][1] = r4[1];
                bf[nt2*2+1][0] = r4[2]; bf[nt2*2+1][1] = r4[3];
            }
            #pragma unroll
            for (int mt = 0; mt < 4; ++mt)
                #pragma unroll
                for (int nt = 0; nt < 4; ++nt)
                    mma_f16(acc[mt][nt], af[mt], bf[nt]);
        }
        asm volatile("cp.async.wait_group 2;" ::: "memory");
        __syncthreads();
    }

    // Epilogue
    #pragma unroll
    for (int mt = 0; mt < 4; ++mt) {
        const int ml = m0 + wm * 64 + mt * 16 + gidr;
        const int mh = ml + 8;
        float scl, ttl, sch, tth;
        if (BN) {
            scl = g_[ml] * rsqrtf(va_[ml] + 1e-5f);
            ttl = be_[ml] - me_[ml] * scl;
            sch = g_[mh] * rsqrtf(va_[mh] + 1e-5f);
            tth = be_[mh] - me_[mh] * sch;
        } else { scl = uscale; ttl = 0.f; sch = uscale; tth = 0.f; }
        #pragma unroll
        for (int nt = 0; nt < 4; ++nt) {
            const int nn = n0 + wn * 32 + nt * 8 + 2 * t4;
            float2 vl, vh;
            vl.x = acc[mt][nt][0] * scl + ttl;
            vl.y = acc[mt][nt][1] * scl + ttl;
            vh.x = acc[mt][nt][2] * sch + tth;
            vh.y = acc[mt][nt][3] * sch + tth;
            if (RELU) {
                vl.x = fmaxf(vl.x, 0.f); vl.y = fmaxf(vl.y, 0.f);
                vh.x = fmaxf(vh.x, 0.f); vh.y = fmaxf(vh.y, 0.f);
            }
            if (HALF_OUT) {
                __half* oh = (__half*)ouse + (size_t)b * ostr;
                *(__half2*)(oh + (size_t)ml * HW + nn) = __floats2half2_rn(vl.x, vl.y);
                *(__half2*)(oh + (size_t)mh * HW + nn) = __floats2half2_rn(vh.x, vh.y);
            } else {
                float* of = (float*)ouse + (size_t)b * ostr;
                if (RESID) {
                    const float* rp = resid + (size_t)b * ostr;
                    float2 rl = *(const float2*)(rp + (size_t)ml * HW + nn);
                    float2 rh = *(const float2*)(rp + (size_t)mh * HW + nn);
                    vl.x += rl.x; vl.y += rl.y; vh.x += rh.x; vh.y += rh.y;
                }
                *(float2*)(of + (size_t)ml * HW + nn) = vl;
                *(float2*)(of + (size_t)mh * HW + nn) = vh;
            }
        }
    }
}

// ---------------------------------------------------------------------------
// attn_out: y[b][c][n] = sum_s Vp[b][c][s] * P[b][s][n]  (K=112 single shot)
// ---------------------------------------------------------------------------
#define AO_ASTR 120
#define AO_SMEM (128*AO_ASTR*2 + 112*B_STRH*2)   // 61184

__global__ __launch_bounds__(256, 2) void attn_out_kernel(
    const __half* __restrict__ Vp, const __half* __restrict__ P, __half* __restrict__ y)
{
    extern __shared__ __align__(16) char smc[];
    const uint32_t sb = smem_u32(smc);
    const uint32_t sA = sb, sB = sb + 128*AO_ASTR*2;
    const int tid = threadIdx.x, lane = tid & 31, wid = tid >> 5;
    const int gidr = lane >> 2, t4 = lane & 3;
    const int wm = wid >> 2, wn = wid & 3;
    const int n0 = blockIdx.x * 128, c0 = blockIdx.y * 128, b = blockIdx.z;

    const __half* gA = Vp + (size_t)b * CV * 112 + (size_t)c0 * 112;
    const __half* gB = P + (size_t)b * 112 * HW + n0;

    #pragma unroll
    for (int it = 0; it < 7; ++it) {
        int idx = it * 256 + tid;
        int r = idx / 14, c = idx - r * 14;
        cpa16(sA + (uint32_t)(r * AO_ASTR + c * 8) * 2, gA + (size_t)r * 112 + c * 8);
    }
    #pragma unroll
    for (int it = 0; it < 7; ++it) {
        int idx = it * 256 + tid;
        int r = idx >> 4, c = idx & 15;
        cpa16(sB + (uint32_t)(r * B_STRH + c * 8) * 2, gB + (size_t)r * HW + c * 8);
    }
    asm volatile("cp.async.commit_group;\ncp.async.wait_group 0;" ::: "memory");
    __syncthreads();

    const int a_row = lane & 15, a_koff = (lane >> 4) * 8;
    const int b_krow = ((lane >> 3) & 1) * 8 + (lane & 7);
    const int b_noff = (lane >> 4) * 8;

    float acc[4][4][4];
    #pragma unroll
    for (int mt = 0; mt < 4; ++mt)
        #pragma unroll
        for (int nt = 0; nt < 4; ++nt)
            #pragma unroll
            for (int r = 0; r < 4; ++r) acc[mt][nt][r] = 0.f;

    #pragma unroll
    for (int s16 = 0; s16 < 7; ++s16) {
        const int kk = s16 * 16;
        uint32_t af[4][4], bf[4][2];
        #pragma unroll
        for (int mt = 0; mt < 4; ++mt) {
            int row = wm * 64 + mt * 16 + a_row;
            ldsm_x4(af[mt], sA + (uint32_t)(row * AO_ASTR + kk + a_koff) * 2);
        }
        #pragma unroll
        for (int nt2 = 0; nt2 < 2; ++nt2) {
            uint32_t r4[4];
            int ncol = wn * 32 + nt2 * 16 + b_noff;
            ldsm_x4_t(r4, sB + (uint32_t)((kk + b_krow) * B_STRH + ncol) * 2);
            bf[nt2*2][0] = r4[0]; bf[nt2*2][1] = r4[1];
            bf[nt2*2+1][0] = r4[2]; bf[nt2*2+1][1] = r4[3];
        }
        #pragma unroll
        for (int mt = 0; mt < 4; ++mt)
            #pragma unroll
            for (int nt = 0; nt < 4; ++nt)
                mma_f16(acc[mt][nt], af[mt], bf[nt]);
    }

    __half* yb = y + (size_t)b * CV * HW;
    #pragma unroll
    for (int mt = 0; mt < 4; ++mt) {
        const int ml = c0 + wm * 64 + mt * 16 + gidr;
        #pragma unroll
        for (int nt = 0; nt < 4; ++nt) {
            const int nn = n0 + wn * 32 + nt * 8 + 2 * t4;
            *(__half2*)(yb + (size_t)ml * HW + nn) =
                __floats2half2_rn(acc[mt][nt][0], acc[mt][nt][1]);
            *(__half2*)(yb + (size_t)(ml + 8) * HW + nn) =
                __floats2half2_rn(acc[mt][nt][2], acc[mt][nt][3]);
        }
    }
}

// ---------------------------------------------------------------------------
// Weight + x fp16 conversions
// ---------------------------------------------------------------------------
__global__ __launch_bounds__(256) void cvt_weights_kernel(
    const float* __restrict__ wq, const float* __restrict__ wv,
    const float* __restrict__ wo,
    __half* __restrict__ oq, __half* __restrict__ ov, __half* __restrict__ oo)
{
    int i = blockIdx.x * 256 + threadIdx.x;
    if (i < CK*CIN) oq[i] = __float2half_rn(wq[i]);
    if (i < CV*CIN) { ov[i] = __float2half_rn(wv[i]); oo[i] = __float2half_rn(wo[i]); }
}
__global__ __launch_bounds__(256) void cvt_half_v8_kernel(
    const float4* __restrict__ a, uint4* __restrict__ o, int n8)
{
    int i = blockIdx.x * 256 + threadIdx.x;
    if (i < n8) {
        float4 f0 = a[2*i], f1 = a[2*i+1];
        __half2 h0 = __floats2half2_rn(f0.x, f0.y);
        __half2 h1 = __floats2half2_rn(f0.z, f0.w);
        __half2 h2 = __floats2half2_rn(f1.x, f1.y);
        __half2 h3 = __floats2half2_rn(f1.z, f1.w);
        uint4 u;
        u.x = *(uint32_t*)&h0; u.y = *(uint32_t*)&h1;
        u.z = *(uint32_t*)&h2; u.w = *(uint32_t*)&h3;
        o[i] = u;
    }
}

// ---------------------------------------------------------------------------
// PSP adaptive max pool, BOTH tensors in one launch. Plane kept in fp16 smem
// (stride 66 halves: conflict-free), rm in fp32 (stride 65), 2 planes per
// 256-thread block -> 26KB smem -> 8 CTAs/SM.
// blocks [0, BB*CK/2):  qk  -> key  out[(b*128 + cell)*CK + c]
// blocks [BB*CK/2, ..): val -> vpsp out[(b*CV + c)*112 + cell]
// ---------------------------------------------------------------------------
#define SPH_STR 66
#define RM_STR  65
#define QK_BLOCKS (BB*CK/2)          // 1024
#define PSP_BLOCKS (BB*(CK+CV)/2)    // 3072

__global__ __launch_bounds__(256) void psp_kernel(
    const __half* __restrict__ qk_in, __half* __restrict__ key_out,
    const __half* __restrict__ val_in, __half* __restrict__ val_out)
{
    __shared__ __align__(16) __half sph[2][64 * SPH_STR];
    __shared__ float rm[2][17 * RM_STR];
    __shared__ float s8v[2][64];
    const int pl = threadIdx.x >> 7;
    const int tid = threadIdx.x & 127;

    const __half* in; __half* out; int C, mode, bc;
    if (blockIdx.x < QK_BLOCKS) {
        in = qk_in; out = key_out; C = CK; mode = 1;
        bc = blockIdx.x * 2 + pl;
    } else {
        in = val_in; out = val_out; C = CV; mode = 0;
        bc = (blockIdx.x - QK_BLOCKS) * 2 + pl;
    }
    const int b = bc / C, c = bc - b * C;
    __half* spp = sph[pl];
    float* rmp = rm[pl];
    const __half* plane = in + (size_t)bc * 4096;

    // Load plane: rows of 64 halves at stride 66. Store 8 halves as 4x b32
    // (row byte-stride 132 is only 4B-aligned). Banks distinct across warp.
    for (int i = tid; i < 512; i += 128) {
        uint4 u = ((const uint4*)plane)[i];
        int row = i >> 3, col = (i & 7) * 8;
        uint32_t* d = (uint32_t*)(spp + row * SPH_STR + col);
        d[0] = u.x; d[1] = u.y; d[2] = u.z; d[3] = u.w;
    }
    __syncthreads();

    // Phase 1: per-(seg,row) column-range maxes. Lanes = consecutive rows,
    // banks (33*row + cc/2) mod 32 -> distinct: conflict-free.
    const int cs[17] = {0,21,42, 0,10,21,32,42,53, 0,8,16,24,32,40,48,56};
    const int ce[17] = {22,43,64, 11,22,32,43,54,64, 8,16,24,32,40,48,56,64};
    for (int idx = tid; idx < 17 * 64; idx += 128) {
        int seg = idx >> 6, row = idx & 63;
        const __half* rp = spp + row * SPH_STR;
        float m = -3.402823e38f;
        for (int cc = cs[seg]; cc < ce[seg]; ++cc)
            m = fmaxf(m, __half2float(rp[cc]));
        rmp[seg * RM_STR + row] = m;
    }
    __syncthreads();

    // Phase 2: cells
    float m = -3.402823e38f;
    int cell = -1;
    if (tid < 64) {                        // s=8
        int i = tid >> 3, j = tid & 7;
        for (int r = i * 8; r < i * 8 + 8; ++r) m = fmaxf(m, rmp[(9 + j) * RM_STR + r]);
        s8v[pl][tid] = m; cell = 46 + tid;
    } else if (tid < 100) {                // s=6
        const int st[6] = {0,10,21,32,42,53}, en[6] = {11,22,32,43,54,64};
        int t = tid - 64, i = t / 6, j = t - i * 6;
        for (int r = st[i]; r < en[i]; ++r) m = fmaxf(m, rmp[(3 + j) * RM_STR + r]);
        cell = 10 + t;
    } else if (tid < 109) {                // s=3
        const int st[3] = {0,21,42}, en[3] = {22,43,64};
        int t = tid - 100, i = t / 3, j = t - i * 3;
        for (int r = st[i]; r < en[i]; ++r) m = fmaxf(m, rmp[j * RM_STR + r]);
        cell = 1 + t;
    }
    if (cell >= 0) {
        size_t o = mode ? ((size_t)(b * 128 + cell) * C + c)
                        : ((size_t)bc * 112 + cell);
        out[o] = __float2half_rn(m);
    }
    __syncthreads();
    if (tid == 0) {                        // s=1 from the 64 exact 8x8 cells
        float mm = s8v[pl][0];
        for (int i = 1; i < 64; ++i) mm = fmaxf(mm, s8v[pl][i]);
        size_t o = mode ? ((size_t)(b * 128) * C + c) : ((size_t)bc * 112);
        out[o] = __float2half_rn(mm);
    }
}

// ---------------------------------------------------------------------------
// Column softmax over s (110) for each n.
// ---------------------------------------------------------------------------
__global__ __launch_bounds__(128) void softmax_kernel(
    const __half* __restrict__ s_h, __half* __restrict__ p_h)
{
    __shared__ __align__(16) __half ss[SS * 128];
    const int b = blockIdx.y, n0 = blockIdx.x * 128;
    const int tid = threadIdx.x;
    const __half* sbx = s_h + (size_t)b * 128 * HW + n0;
    for (int i = tid; i < SS * 16; i += 128) {
        int row = i >> 4, col = (i & 15) * 8;
        *(uint4*)&ss[row * 128 + col] = *(const uint4*)&sbx[(size_t)row * HW + col];
    }
    __syncthreads();

    float mx = -3.402823e38f;
    #pragma unroll 2
    for (int s = 0; s < SS; ++s) mx = fmaxf(mx, __half2float(ss[s * 128 + tid]));
    float sum = 0.f;
    #pragma unroll 2
    for (int s = 0; s < SS; ++s) sum += __expf(__half2float(ss[s * 128 + tid]) - mx);
    const float inv = 1.f / sum;
    __half* pb = p_h + (size_t)b * 112 * HW + n0 + tid;
    #pragma unroll 2
    for (int s = 0; s < SS; ++s)
        pb[(size_t)s * HW] = __float2half_rn(__expf(__half2float(ss[s * 128 + tid]) - mx) * inv);
}

// ---------------------------------------------------------------------------
extern "C" void kernel_launch(void* const* d_in, const int* in_sizes, int n_in,
                              void* d_out, int out_size)
{
    const float* x        = (const float*)d_in[0];
    const float* qk_w     = (const float*)d_in[1];
    const float* qk_gamma = (const float*)d_in[2];
    const float* qk_beta  = (const float*)d_in[3];
    const float* qk_mean  = (const float*)d_in[4];
    const float* qk_var   = (const float*)d_in[5];
    const float* v_w      = (const float*)d_in[6];
    const float* v_gamma  = (const float*)d_in[7];
    const float* v_beta   = (const float*)d_in[8];
    const float* v_mean   = (const float*)d_in[9];
    const float* v_var    = (const float*)d_in[10];
    const float* out_w    = (const float*)d_in[11];
    const float* o_gamma  = (const float*)d_in[12];
    const float* o_beta   = (const float*)d_in[13];
    const float* o_mean   = (const float*)d_in[14];
    const float* o_var    = (const float*)d_in[15];
    float* out = (float*)d_out;

    __half *xh, *qkh, *valh, *keyh, *vpsp, *sh, *ph, *yh, *wq, *wv, *wo;
    cudaGetSymbolAddress((void**)&xh,   g_xh);
    cudaGetSymbolAddress((void**)&qkh,  g_qkh);
    cudaGetSymbolAddress((void**)&valh, g_valh);
    cudaGetSymbolAddress((void**)&keyh, g_keyh);
    cudaGetSymbolAddress((void**)&vpsp, g_vpsp);
    cudaGetSymbolAddress((void**)&sh,   g_sh);
    cudaGetSymbolAddress((void**)&ph,   g_ph);
    cudaGetSymbolAddress((void**)&yh,   g_yh);
    cudaGetSymbolAddress((void**)&wq,   g_wq);
    cudaGetSymbolAddress((void**)&wv,   g_wv);
    cudaGetSymbolAddress((void**)&wo,   g_wo);

    cudaFuncSetAttribute(gemm_kernel<true, true, true, false, true>,
                         cudaFuncAttributeMaxDynamicSharedMemorySize, GEMM_SMEM);
    cudaFuncSetAttribute(gemm_kernel<false, false, false, false, true>,
                         cudaFuncAttributeMaxDynamicSharedMemorySize, GEMM_SMEM);
    cudaFuncSetAttribute(gemm_kernel<false, true, false, true, false>,
                         cudaFuncAttributeMaxDynamicSharedMemorySize, GEMM_SMEM);
    cudaFuncSetAttribute(attn_out_kernel,
                         cudaFuncAttributeMaxDynamicSharedMemorySize, AO_SMEM);

    // 0) fp16 conversions
    cvt_weights_kernel<<<(CV*CIN + 255) / 256, 256>>>(qk_w, v_w, out_w, wq, wv, wo);
    cvt_half_v8_kernel<<<(BB*CIN*HW/8 + 255) / 256, 256>>>(
        (const float4*)x, (uint4*)xh, BB*CIN*HW/8);

    // 1+2) fused: qk = relu(bn(conv(x,wq))), val = relu(bn(conv(x,wv)))
    gemm_kernel<true, true, true, false, true><<<dim3(32, 6, BB), 256, GEMM_SMEM>>>(
        wq, 0, xh, (size_t)CIN*HW, qk_gamma, qk_beta, qk_mean, qk_var,
        1.f, nullptr, qkh, (size_t)CK*HW, CIN,
        wv, v_gamma, v_beta, v_mean, v_var, valh, (size_t)CV*HW);
    // 3) key = psp(qk) [s][c]  AND  value = psp(val) [c][s]  (one launch)
    psp_kernel<<<PSP_BLOCKS, 256>>>(qkh, keyh, valh, vpsp);
    // 4) raw scores [s][n] = (key @ qk) / 16
    gemm_kernel<false, false, false, false, true><<<dim3(32, 1, BB), 256, GEMM_SMEM>>>(
        keyh, (size_t)128*CK, qkh, (size_t)CK*HW, nullptr, nullptr, nullptr, nullptr,
        0.0625f, nullptr, sh, (size_t)128*HW, CK,
        nullptr, nullptr, nullptr, nullptr, nullptr, nullptr, 0);
    // 5) column softmax -> p [s][n] half
    softmax_kernel<<<dim3(32, BB), 128>>>(sh, ph);
    // 6) y[c][n] = value[c][s] @ p[s][n]
    attn_out_kernel<<<dim3(32, 4, BB), 256, AO_SMEM>>>(vpsp, ph, yh);
    // 7) out = x + bn(conv(y, wo))
    gemm_kernel<false, true, false, true, false><<<dim3(32, 4, BB), 256, GEMM_SMEM>>>(
        wo, 0, yh, (size_t)CV*HW, o_gamma, o_beta, o_mean, o_var,
        1.f, x, out, (size_t)CIN*HW, CV,
        nullptr, nullptr, nullptr, nullptr, nullptr, nullptr, 0);
}

// round 9
// speedup vs baseline: 5.4770x; 1.0593x over previous
#include <cuda_runtime.h>
#include <cuda_fp16.h>
#include <cstdint>
#include <math.h>

#define BB   8
#define CIN  512
#define CK   256
#define CV   512
#define HW   4096
#define SS   110

// Scratch (__device__ globals are zero-initialized; pad regions never written
// stay zero -> free zero-padding).
__device__ __align__(16) __half g_xh    [BB*CIN*HW];    // [b][k][n]
__device__ __align__(16) __half g_qkh   [BB*CK*HW];     // [b][c][n]
__device__ __align__(16) __half g_valh  [BB*CV*HW];     // [b][c][n]
__device__ __align__(16) __half g_keyh  [BB*128*CK];    // [b][s(pad128)][c]
__device__ __align__(16) __half g_vpsp  [BB*CV*112];    // [b][c][s(pad112)]
__device__ __align__(16) __half g_ph    [BB*112*HW];    // [b][s(pad112)][n]
__device__ __align__(16) __half g_yh    [BB*CV*HW];     // [b][c][n]
__device__ __align__(16) __half g_wq    [CK*CIN];
__device__ __align__(16) __half g_wv    [CV*CIN];
__device__ __align__(16) __half g_wo    [CIN*CV];

// ---------------------------------------------------------------------------
__device__ __forceinline__ uint32_t smem_u32(const void* p) {
    uint32_t a;
    asm("{ .reg .u64 t; cvta.to.shared.u64 t, %1; cvt.u32.u64 %0, t; }" : "=r"(a) : "l"(p));
    return a;
}
__device__ __forceinline__ void ldsm_x4(uint32_t* r, uint32_t addr) {
    asm volatile("ldmatrix.sync.aligned.m8n8.x4.shared.b16 {%0,%1,%2,%3}, [%4];"
        : "=r"(r[0]), "=r"(r[1]), "=r"(r[2]), "=r"(r[3]) : "r"(addr));
}
__device__ __forceinline__ void ldsm_x4_t(uint32_t* r, uint32_t addr) {
    asm volatile("ldmatrix.sync.aligned.m8n8.x4.trans.shared.b16 {%0,%1,%2,%3}, [%4];"
        : "=r"(r[0]), "=r"(r[1]), "=r"(r[2]), "=r"(r[3]) : "r"(addr));
}
__device__ __forceinline__ void mma_f16(float* c, const uint32_t* a, const uint32_t* b) {
    asm volatile(
        "mma.sync.aligned.m16n8k16.row.col.f32.f16.f16.f32 "
        "{%0,%1,%2,%3}, {%4,%5,%6,%7}, {%8,%9}, {%0,%1,%2,%3};"
        : "+f"(c[0]), "+f"(c[1]), "+f"(c[2]), "+f"(c[3])
        : "r"(a[0]), "r"(a[1]), "r"(a[2]), "r"(a[3]), "r"(b[0]), "r"(b[1]));
}
__device__ __forceinline__ void cpa16(uint32_t dst, const void* src) {
    asm volatile("cp.async.cg.shared.global [%0], [%1], 16;" :: "r"(dst), "l"(src));
}

// ---------------------------------------------------------------------------
// Generalized GEMM: out[b,m,n] = epi( sum_k A[m,k] * B[b,k,n] )
// CTA 128m x 128n, 8 warps (2x4), warp 64x32. K staged 32, 4-stage pipeline.
// FUSED: blockIdx.y<2 -> branch 1, else branch 2.
// SOFTMAX: epilogue computes column-softmax over m (valid rows < SS) and
//          writes fp16 probabilities directly (rows [SS,112) written 0).
// ---------------------------------------------------------------------------
#define A_STRH 40
#define B_STRH 136
#define A_STG  (128*A_STRH*2)              // 10240 B
#define B_STG  (32*B_STRH*2)               // 8704 B
#define STG    (A_STG + B_STG)             // 18944 B
#define NSTAGE 4
#define GEMM_SMEM (NSTAGE*STG)             // 75776 B

template<bool FUSED, bool BN, bool RELU, bool RESID, bool HALF_OUT, bool SOFTMAX>
__global__ __launch_bounds__(256, 2) void gemm_kernel(
    const __half* __restrict__ A, size_t a_bstride,
    const __half* __restrict__ Bm, size_t b_bstride,
    const float* __restrict__ gamma, const float* __restrict__ beta,
    const float* __restrict__ mean,  const float* __restrict__ var,
    float uscale,
    const float* __restrict__ resid,
    void* __restrict__ outp, size_t o_bstride,
    int Ktot,
    // FUSED branch-2 args
    const __half* __restrict__ A2,
    const float* __restrict__ gamma2, const float* __restrict__ beta2,
    const float* __restrict__ mean2,  const float* __restrict__ var2,
    void* __restrict__ outp2, size_t o_bstride2)
{
    extern __shared__ __align__(16) char smc[];
    const uint32_t sb = smem_u32(smc);
    const int tid = threadIdx.x, lane = tid & 31, wid = tid >> 5;
    const int gidr = lane >> 2, t4 = lane & 3;
    const int wm = wid >> 2, wn = wid & 3;
    const int n0 = blockIdx.x * 128, b = blockIdx.z;
    const int NK = Ktot >> 5;

    int m0 = blockIdx.y * 128;
    const __half* Ause = A;
    const float *g_ = gamma, *be_ = beta, *me_ = mean, *va_ = var;
    void* ouse = outp;
    size_t ostr = o_bstride;
    if (FUSED && blockIdx.y >= 2) {
        m0 = (blockIdx.y - 2) * 128;
        Ause = A2; g_ = gamma2; be_ = beta2; me_ = mean2; va_ = var2;
        ouse = outp2; ostr = o_bstride2;
    }

    const __half* gA = Ause + (size_t)b * a_bstride + (size_t)m0 * Ktot;
    const __half* gB = Bm + (size_t)b * b_bstride + n0;

    auto load_stage = [&](int s) {
        const uint32_t base = sb + (uint32_t)(s & (NSTAGE-1)) * STG;
        #pragma unroll
        for (int it = 0; it < 2; ++it) {            // A: 128r x 4 chunks
            int idx = it * 256 + tid;
            int r = idx >> 2, c = idx & 3;
            cpa16(base + (uint32_t)(r * A_STRH + c * 8) * 2,
                  gA + (size_t)r * Ktot + s * 32 + c * 8);
        }
        #pragma unroll
        for (int it = 0; it < 2; ++it) {            // B: 32r x 16 chunks
            int idx = it * 256 + tid;
            int r = idx >> 4, c = idx & 15;
            cpa16(base + A_STG + (uint32_t)(r * B_STRH + c * 8) * 2,
                  gB + (size_t)(s * 32 + r) * HW + c * 8);
        }
        asm volatile("cp.async.commit_group;" ::: "memory");
    };

    float acc[4][4][4];
    #pragma unroll
    for (int mt = 0; mt < 4; ++mt)
        #pragma unroll
        for (int nt = 0; nt < 4; ++nt)
            #pragma unroll
            for (int r = 0; r < 4; ++r) acc[mt][nt][r] = 0.f;

    for (int s = 0; s < NSTAGE - 1 && s < NK; ++s) load_stage(s);
    asm volatile("cp.async.wait_group 2;" ::: "memory");
    __syncthreads();

    const int a_row = lane & 15, a_koff = (lane >> 4) * 8;
    const int b_krow = ((lane >> 3) & 1) * 8 + (lane & 7);
    const int b_noff = (lane >> 4) * 8;

    for (int kt = 0; kt < NK; ++kt) {
        if (kt + NSTAGE - 1 < NK) load_stage(kt + NSTAGE - 1);
        else asm volatile("cp.async.commit_group;" ::: "memory");

        const uint32_t sA = sb + (uint32_t)(kt & (NSTAGE-1)) * STG;
        const uint32_t sB = sA + A_STG;
        #pragma unroll
        for (int s16 = 0; s16 < 2; ++s16) {
            const int kk = s16 * 16;
            uint32_t af[4][4], bf[4][2];
            #pragma unroll
            for (int mt = 0; mt < 4; ++mt) {
                int row = wm * 64 + mt * 16 + a_row;
                ldsm_x4(af[mt], sA + (uint32_t)(row * A_STRH + kk + a_koff) * 2);
            }
            #pragma unroll
            for (int nt2 = 0; nt2 < 2; ++nt2) {
                uint32_t r4[4];
                int ncol = wn * 32 + nt2 * 16 + b_noff;
                ldsm_x4_t(r4, sB + (uint32_t)((kk + b_krow) * B_STRH + ncol) * 2);
                bf[nt2*2][0] = r4[0]; bf[nt2*2][1] = r4[1];
                bf[nt2*2+1][0] = r4[2]; bf[nt2*2+1][1] = r4[3];
            }
            #pragma unroll
            for (int mt = 0; mt < 4; ++mt)
                #pragma unroll
                for (int nt = 0; nt < 4; ++nt)
                    mma_f16(acc[mt][nt], af[mt], bf[nt]);
        }
        asm volatile("cp.async.wait_group 2;" ::: "memory");
        __syncthreads();
    }

    if (SOFTMAX) {
        // Column softmax over m rows (m0==0, grid.y==1). Valid rows: < SS.
        float* red = (float*)smc;              // reuse stage smem (512 floats)
        float cmax[4][2], csum[4][2];
        #pragma unroll
        for (int nt = 0; nt < 4; ++nt) { cmax[nt][0] = -3.4e38f; cmax[nt][1] = -3.4e38f; }
        #pragma unroll
        for (int mt = 0; mt < 4; ++mt) {
            const int r0 = wm * 64 + mt * 16 + gidr, r1 = r0 + 8;
            #pragma unroll
            for (int nt = 0; nt < 4; ++nt) {
                #pragma unroll
                for (int r = 0; r < 4; ++r) acc[mt][nt][r] *= uscale;
                if (r0 < SS) {
                    cmax[nt][0] = fmaxf(cmax[nt][0], acc[mt][nt][0]);
                    cmax[nt][1] = fmaxf(cmax[nt][1], acc[mt][nt][1]);
                }
                if (r1 < SS) {
                    cmax[nt][0] = fmaxf(cmax[nt][0], acc[mt][nt][2]);
                    cmax[nt][1] = fmaxf(cmax[nt][1], acc[mt][nt][3]);
                }
            }
        }
        #pragma unroll
        for (int nt = 0; nt < 4; ++nt)
            #pragma unroll
            for (int j = 0; j < 2; ++j) {
                float v = cmax[nt][j];
                v = fmaxf(v, __shfl_xor_sync(0xffffffffu, v, 4));
                v = fmaxf(v, __shfl_xor_sync(0xffffffffu, v, 8));
                v = fmaxf(v, __shfl_xor_sync(0xffffffffu, v, 16));
                cmax[nt][j] = v;
            }
        if (gidr == 0)
            #pragma unroll
            for (int nt = 0; nt < 4; ++nt)
                #pragma unroll
                for (int j = 0; j < 2; ++j)
                    red[wm*128 + wn*32 + nt*8 + 2*t4 + j] = cmax[nt][j];
        __syncthreads();
        #pragma unroll
        for (int nt = 0; nt < 4; ++nt)
            #pragma unroll
            for (int j = 0; j < 2; ++j)
                cmax[nt][j] = fmaxf(cmax[nt][j], red[(wm^1)*128 + wn*32 + nt*8 + 2*t4 + j]);

        #pragma unroll
        for (int nt = 0; nt < 4; ++nt) { csum[nt][0] = 0.f; csum[nt][1] = 0.f; }
        #pragma unroll
        for (int mt = 0; mt < 4; ++mt) {
            const int r0 = wm * 64 + mt * 16 + gidr, r1 = r0 + 8;
            #pragma unroll
            for (int nt = 0; nt < 4; ++nt) {
                float e0 = (r0 < SS) ? __expf(acc[mt][nt][0] - cmax[nt][0]) : 0.f;
                float e1 = (r0 < SS) ? __expf(acc[mt][nt][1] - cmax[nt][1]) : 0.f;
                float e2 = (r1 < SS) ? __expf(acc[mt][nt][2] - cmax[nt][0]) : 0.f;
                float e3 = (r1 < SS) ? __expf(acc[mt][nt][3] - cmax[nt][1]) : 0.f;
                acc[mt][nt][0] = e0; acc[mt][nt][1] = e1;
                acc[mt][nt][2] = e2; acc[mt][nt][3] = e3;
                csum[nt][0] += e0 + e2; csum[nt][1] += e1 + e3;
            }
        }
        #pragma unroll
        for (int nt = 0; nt < 4; ++nt)
            #pragma unroll
            for (int j = 0; j < 2; ++j) {
                float v = csum[nt][j];
                v += __shfl_xor_sync(0xffffffffu, v, 4);
                v += __shfl_xor_sync(0xffffffffu, v, 8);
                v += __shfl_xor_sync(0xffffffffu, v, 16);
                csum[nt][j] = v;
            }
        if (gidr == 0)
            #pragma unroll
            for (int nt = 0; nt < 4; ++nt)
                #pragma unroll
                for (int j = 0; j < 2; ++j)
                    red[256 + wm*128 + wn*32 + nt*8 + 2*t4 + j] = csum[nt][j];
        __syncthreads();
        #pragma unroll
        for (int nt = 0; nt < 4; ++nt)
            #pragma unroll
            for (int j = 0; j < 2; ++j)
                csum[nt][j] += red[256 + (wm^1)*128 + wn*32 + nt*8 + 2*t4 + j];

        __half* oh = (__half*)ouse + (size_t)b * ostr;
        #pragma unroll
        for (int mt = 0; mt < 4; ++mt) {
            const int r0 = wm * 64 + mt * 16 + gidr, r1 = r0 + 8;
            #pragma unroll
            for (int nt = 0; nt < 4; ++nt) {
                const int nn = n0 + wn * 32 + nt * 8 + 2 * t4;
                const float i0 = 1.f / csum[nt][0], i1 = 1.f / csum[nt][1];
                if (r0 < 112)
                    *(__half2*)(oh + (size_t)r0 * HW + nn) =
                        __floats2half2_rn(acc[mt][nt][0] * i0, acc[mt][nt][1] * i1);
                if (r1 < 112)
                    *(__half2*)(oh + (size_t)r1 * HW + nn) =
                        __floats2half2_rn(acc[mt][nt][2] * i0, acc[mt][nt][3] * i1);
            }
        }
        return;
    }

    // Standard epilogue
    #pragma unroll
    for (int mt = 0; mt < 4; ++mt) {
        const int ml = m0 + wm * 64 + mt * 16 + gidr;
        const int mh = ml + 8;
        float scl, ttl, sch, tth;
        if (BN) {
            scl = g_[ml] * rsqrtf(va_[ml] + 1e-5f);
            ttl = be_[ml] - me_[ml] * scl;
            sch = g_[mh] * rsqrtf(va_[mh] + 1e-5f);
            tth = be_[mh] - me_[mh] * sch;
        } else { scl = uscale; ttl = 0.f; sch = uscale; tth = 0.f; }
        #pragma unroll
        for (int nt = 0; nt < 4; ++nt) {
            const int nn = n0 + wn * 32 + nt * 8 + 2 * t4;
            float2 vl, vh;
            vl.x = acc[mt][nt][0] * scl + ttl;
            vl.y = acc[mt][nt][1] * scl + ttl;
            vh.x = acc[mt][nt][2] * sch + tth;
            vh.y = acc[mt][nt][3] * sch + tth;
            if (RELU) {
                vl.x = fmaxf(vl.x, 0.f); vl.y = fmaxf(vl.y, 0.f);
                vh.x = fmaxf(vh.x, 0.f); vh.y = fmaxf(vh.y, 0.f);
            }
            if (HALF_OUT) {
                __half* oh = (__half*)ouse + (size_t)b * ostr;
                *(__half2*)(oh + (size_t)ml * HW + nn) = __floats2half2_rn(vl.x, vl.y);
                *(__half2*)(oh + (size_t)mh * HW + nn) = __floats2half2_rn(vh.x, vh.y);
            } else {
                float* of = (float*)ouse + (size_t)b * ostr;
                if (RESID) {
                    const float* rp = resid + (size_t)b * ostr;
                    float2 rl = *(const float2*)(rp + (size_t)ml * HW + nn);
                    float2 rh = *(const float2*)(rp + (size_t)mh * HW + nn);
                    vl.x += rl.x; vl.y += rl.y; vh.x += rh.x; vh.y += rh.y;
                }
                *(float2*)(of + (size_t)ml * HW + nn) = vl;
                *(float2*)(of + (size_t)mh * HW + nn) = vh;
            }
        }
    }
}

// ---------------------------------------------------------------------------
// attn_out: y[b][c][n] = sum_s Vp[b][c][s] * P[b][s][n]  (K=112 single shot)
// ---------------------------------------------------------------------------
#define AO_ASTR 120
#define AO_SMEM (128*AO_ASTR*2 + 112*B_STRH*2)   // 61184

__global__ __launch_bounds__(256, 2) void attn_out_kernel(
    const __half* __restrict__ Vp, const __half* __restrict__ P, __half* __restrict__ y)
{
    extern __shared__ __align__(16) char smc[];
    const uint32_t sb = smem_u32(smc);
    const uint32_t sA = sb, sB = sb + 128*AO_ASTR*2;
    const int tid = threadIdx.x, lane = tid & 31, wid = tid >> 5;
    const int gidr = lane >> 2, t4 = lane & 3;
    const int wm = wid >> 2, wn = wid & 3;
    const int n0 = blockIdx.x * 128, c0 = blockIdx.y * 128, b = blockIdx.z;

    const __half* gA = Vp + (size_t)b * CV * 112 + (size_t)c0 * 112;
    const __half* gB = P + (size_t)b * 112 * HW + n0;

    #pragma unroll
    for (int it = 0; it < 7; ++it) {
        int idx = it * 256 + tid;
        int r = idx / 14, c = idx - r * 14;
        cpa16(sA + (uint32_t)(r * AO_ASTR + c * 8) * 2, gA + (size_t)r * 112 + c * 8);
    }
    #pragma unroll
    for (int it = 0; it < 7; ++it) {
        int idx = it * 256 + tid;
        int r = idx >> 4, c = idx & 15;
        cpa16(sB + (uint32_t)(r * B_STRH + c * 8) * 2, gB + (size_t)r * HW + c * 8);
    }
    asm volatile("cp.async.commit_group;\ncp.async.wait_group 0;" ::: "memory");
    __syncthreads();

    const int a_row = lane & 15, a_koff = (lane >> 4) * 8;
    const int b_krow = ((lane >> 3) & 1) * 8 + (lane & 7);
    const int b_noff = (lane >> 4) * 8;

    float acc[4][4][4];
    #pragma unroll
    for (int mt = 0; mt < 4; ++mt)
        #pragma unroll
        for (int nt = 0; nt < 4; ++nt)
            #pragma unroll
            for (int r = 0; r < 4; ++r) acc[mt][nt][r] = 0.f;

    #pragma unroll
    for (int s16 = 0; s16 < 7; ++s16) {
        const int kk = s16 * 16;
        uint32_t af[4][4], bf[4][2];
        #pragma unroll
        for (int mt = 0; mt < 4; ++mt) {
            int row = wm * 64 + mt * 16 + a_row;
            ldsm_x4(af[mt], sA + (uint32_t)(row * AO_ASTR + kk + a_koff) * 2);
        }
        #pragma unroll
        for (int nt2 = 0; nt2 < 2; ++nt2) {
            uint32_t r4[4];
            int ncol = wn * 32 + nt2 * 16 + b_noff;
            ldsm_x4_t(r4, sB + (uint32_t)((kk + b_krow) * B_STRH + ncol) * 2);
            bf[nt2*2][0] = r4[0]; bf[nt2*2][1] = r4[1];
            bf[nt2*2+1][0] = r4[2]; bf[nt2*2+1][1] = r4[3];
        }
        #pragma unroll
        for (int mt = 0; mt < 4; ++mt)
            #pragma unroll
            for (int nt = 0; nt < 4; ++nt)
                mma_f16(acc[mt][nt], af[mt], bf[nt]);
    }

    __half* yb = y + (size_t)b * CV * HW;
    #pragma unroll
    for (int mt = 0; mt < 4; ++mt) {
        const int ml = c0 + wm * 64 + mt * 16 + gidr;
        #pragma unroll
        for (int nt = 0; nt < 4; ++nt) {
            const int nn = n0 + wn * 32 + nt * 8 + 2 * t4;
            *(__half2*)(yb + (size_t)ml * HW + nn) =
                __floats2half2_rn(acc[mt][nt][0], acc[mt][nt][1]);
            *(__half2*)(yb + (size_t)(ml + 8) * HW + nn) =
                __floats2half2_rn(acc[mt][nt][2], acc[mt][nt][3]);
        }
    }
}

// ---------------------------------------------------------------------------
// All fp16 conversions in ONE launch: blocks [0,8192) convert x (v8),
// blocks [8192, 9216) convert the three weight matrices.
// ---------------------------------------------------------------------------
#define XV8 (BB*CIN*HW/8)     // 2097152 -> 8192 blocks
__global__ __launch_bounds__(256) void cvt_all_kernel(
    const float4* __restrict__ x, uint4* __restrict__ xh,
    const float* __restrict__ wq, const float* __restrict__ wv,
    const float* __restrict__ wo,
    __half* __restrict__ oq, __half* __restrict__ ov, __half* __restrict__ oo)
{
    if (blockIdx.x < 8192) {
        int i = blockIdx.x * 256 + threadIdx.x;
        float4 f0 = x[2*i], f1 = x[2*i+1];
        __half2 h0 = __floats2half2_rn(f0.x, f0.y);
        __half2 h1 = __floats2half2_rn(f0.z, f0.w);
        __half2 h2 = __floats2half2_rn(f1.x, f1.y);
        __half2 h3 = __floats2half2_rn(f1.z, f1.w);
        uint4 u;
        u.x = *(uint32_t*)&h0; u.y = *(uint32_t*)&h1;
        u.z = *(uint32_t*)&h2; u.w = *(uint32_t*)&h3;
        xh[i] = u;
    } else {
        int i = (blockIdx.x - 8192) * 256 + threadIdx.x;
        if (i < CK*CIN) oq[i] = __float2half_rn(wq[i]);
        if (i < CV*CIN) { ov[i] = __float2half_rn(wv[i]); oo[i] = __float2half_rn(wo[i]); }
    }
}

// ---------------------------------------------------------------------------
// PSP adaptive max pool, BOTH tensors in one launch. Plane in fp16 smem
// (stride 66), phase-1 vectorized with __hmax2. 2 planes per 256-thread block.
// ---------------------------------------------------------------------------
#define SPH_STR 66
#define RM_STR  65
#define QK_BLOCKS (BB*CK/2)          // 1024
#define PSP_BLOCKS (BB*(CK+CV)/2)    // 3072

__global__ __launch_bounds__(256) void psp_kernel(
    const __half* __restrict__ qk_in, __half* __restrict__ key_out,
    const __half* __restrict__ val_in, __half* __restrict__ val_out)
{
    __shared__ __align__(16) __half sph[2][64 * SPH_STR];
    __shared__ float rm[2][17 * RM_STR];
    __shared__ float s8v[2][64];
    const int pl = threadIdx.x >> 7;
    const int tid = threadIdx.x & 127;

    const __half* in; __half* out; int C, mode, bc;
    if (blockIdx.x < QK_BLOCKS) {
        in = qk_in; out = key_out; C = CK; mode = 1;
        bc = blockIdx.x * 2 + pl;
    } else {
        in = val_in; out = val_out; C = CV; mode = 0;
        bc = (blockIdx.x - QK_BLOCKS) * 2 + pl;
    }
    const int b = bc / C, c = bc - b * C;
    __half* spp = sph[pl];
    float* rmp = rm[pl];
    const __half* plane = in + (size_t)bc * 4096;

    for (int i = tid; i < 512; i += 128) {
        uint4 u = ((const uint4*)plane)[i];
        int row = i >> 3, col = (i & 7) * 8;
        uint32_t* d = (uint32_t*)(spp + row * SPH_STR + col);
        d[0] = u.x; d[1] = u.y; d[2] = u.z; d[3] = u.w;
    }
    __syncthreads();

    // Phase 1: per-(seg,row) column-range maxes, fp16 pairwise.
    const int cs[17] = {0,21,42, 0,10,21,32,42,53, 0,8,16,24,32,40,48,56};
    const int ce[17] = {22,43,64, 11,22,32,43,54,64, 8,16,24,32,40,48,56,64};
    for (int idx = tid; idx < 17 * 64; idx += 128) {
        int seg = idx >> 6, row = idx & 63;
        const __half* rp = spp + row * SPH_STR;
        int a = cs[seg], bnd = ce[seg];
        float m = -3.402823e38f;
        if (a & 1) { m = __half2float(rp[a]); ++a; }
        if (bnd & 1) { m = fmaxf(m, __half2float(rp[bnd - 1])); --bnd; }
        __half2 m2 = __floats2half2_rn(-65504.f, -65504.f);
        const __half2* rp2 = (const __half2*)rp;
        for (int c2 = a >> 1; c2 < (bnd >> 1); ++c2) m2 = __hmax2(m2, rp2[c2]);
        m = fmaxf(m, fmaxf(__low2float(m2), __high2float(m2)));
        rmp[seg * RM_STR + row] = m;
    }
    __syncthreads();

    // Phase 2: cells
    float m = -3.402823e38f;
    int cell = -1;
    if (tid < 64) {                        // s=8
        int i = tid >> 3, j = tid & 7;
        for (int r = i * 8; r < i * 8 + 8; ++r) m = fmaxf(m, rmp[(9 + j) * RM_STR + r]);
        s8v[pl][tid] = m; cell = 46 + tid;
    } else if (tid < 100) {                // s=6
        const int st[6] = {0,10,21,32,42,53}, en[6] = {11,22,32,43,54,64};
        int t = tid - 64, i = t / 6, j = t - i * 6;
        for (int r = st[i]; r < en[i]; ++r) m = fmaxf(m, rmp[(3 + j) * RM_STR + r]);
        cell = 10 + t;
    } else if (tid < 109) {                // s=3
        const int st[3] = {0,21,42}, en[3] = {22,43,64};
        int t = tid - 100, i = t / 3, j = t - i * 3;
        for (int r = st[i]; r < en[i]; ++r) m = fmaxf(m, rmp[j * RM_STR + r]);
        cell = 1 + t;
    }
    if (cell >= 0) {
        size_t o = mode ? ((size_t)(b * 128 + cell) * C + c)
                        : ((size_t)bc * 112 + cell);
        out[o] = __float2half_rn(m);
    }
    __syncthreads();
    if (tid == 0) {                        // s=1 from the 64 exact 8x8 cells
        float mm = s8v[pl][0];
        for (int i = 1; i < 64; ++i) mm = fmaxf(mm, s8v[pl][i]);
        size_t o = mode ? ((size_t)(b * 128) * C + c) : ((size_t)bc * 112);
        out[o] = __float2half_rn(mm);
    }
}

// ---------------------------------------------------------------------------
extern "C" void kernel_launch(void* const* d_in, const int* in_sizes, int n_in,
                              void* d_out, int out_size)
{
    const float* x        = (const float*)d_in[0];
    const float* qk_w     = (const float*)d_in[1];
    const float* qk_gamma = (const float*)d_in[2];
    const float* qk_beta  = (const float*)d_in[3];
    const float* qk_mean  = (const float*)d_in[4];
    const float* qk_var   = (const float*)d_in[5];
    const float* v_w      = (const float*)d_in[6];
    const float* v_gamma  = (const float*)d_in[7];
    const float* v_beta   = (const float*)d_in[8];
    const float* v_mean   = (const float*)d_in[9];
    const float* v_var    = (const float*)d_in[10];
    const float* out_w    = (const float*)d_in[11];
    const float* o_gamma  = (const float*)d_in[12];
    const float* o_beta   = (const float*)d_in[13];
    const float* o_mean   = (const float*)d_in[14];
    const float* o_var    = (const float*)d_in[15];
    float* out = (float*)d_out;

    __half *xh, *qkh, *valh, *keyh, *vpsp, *ph, *yh, *wq, *wv, *wo;
    cudaGetSymbolAddress((void**)&xh,   g_xh);
    cudaGetSymbolAddress((void**)&qkh,  g_qkh);
    cudaGetSymbolAddress((void**)&valh, g_valh);
    cudaGetSymbolAddress((void**)&keyh, g_keyh);
    cudaGetSymbolAddress((void**)&vpsp, g_vpsp);
    cudaGetSymbolAddress((void**)&ph,   g_ph);
    cudaGetSymbolAddress((void**)&yh,   g_yh);
    cudaGetSymbolAddress((void**)&wq,   g_wq);
    cudaGetSymbolAddress((void**)&wv,   g_wv);
    cudaGetSymbolAddress((void**)&wo,   g_wo);

    cudaFuncSetAttribute(gemm_kernel<true, true, true, false, true, false>,
                         cudaFuncAttributeMaxDynamicSharedMemorySize, GEMM_SMEM);
    cudaFuncSetAttribute(gemm_kernel<false, false, false, false, true, true>,
                         cudaFuncAttributeMaxDynamicSharedMemorySize, GEMM_SMEM);
    cudaFuncSetAttribute(gemm_kernel<false, true, false, true, false, false>,
                         cudaFuncAttributeMaxDynamicSharedMemorySize, GEMM_SMEM);
    cudaFuncSetAttribute(attn_out_kernel,
                         cudaFuncAttributeMaxDynamicSharedMemorySize, AO_SMEM);

    // 0) all fp16 conversions, one launch
    cvt_all_kernel<<<8192 + 1024, 256>>>(
        (const float4*)x, (uint4*)xh, qk_w, v_w, out_w, wq, wv, wo);

    // 1+2) fused: qk = relu(bn(conv(x,wq))), val = relu(bn(conv(x,wv)))
    gemm_kernel<true, true, true, false, true, false><<<dim3(32, 6, BB), 256, GEMM_SMEM>>>(
        wq, 0, xh, (size_t)CIN*HW, qk_gamma, qk_beta, qk_mean, qk_var,
        1.f, nullptr, qkh, (size_t)CK*HW, CIN,
        wv, v_gamma, v_beta, v_mean, v_var, valh, (size_t)CV*HW);
    // 3) key = psp(qk) [s][c]  AND  value = psp(val) [c][s]  (one launch)
    psp_kernel<<<PSP_BLOCKS, 256>>>(qkh, keyh, valh, vpsp);
    // 4) P = softmax_s( (key @ qk) / 16 )  -- softmax fused into GEMM epilogue
    gemm_kernel<false, false, false, false, true, true><<<dim3(32, 1, BB), 256, GEMM_SMEM>>>(
        keyh, (size_t)128*CK, qkh, (size_t)CK*HW, nullptr, nullptr, nullptr, nullptr,
        0.0625f, nullptr, ph, (size_t)112*HW, CK,
        nullptr, nullptr, nullptr, nullptr, nullptr, nullptr, 0);
    // 5) y[c][n] = value[c][s] @ p[s][n]
    attn_out_kernel<<<dim3(32, 4, BB), 256, AO_SMEM>>>(vpsp, ph, yh);
    // 6) out = x + bn(conv(y, wo))
    gemm_kernel<false, true, false, true, false, false><<<dim3(32, 4, BB), 256, GEMM_SMEM>>>(
        wo, 0, yh, (size_t)CV*HW, o_gamma, o_beta, o_mean, o_var,
        1.f, x, out, (size_t)CIN*HW, CV,
        nullptr, nullptr, nullptr, nullptr, nullptr, nullptr, 0);
}